// round 2
// baseline (speedup 1.0000x reference)
#include <cuda_runtime.h>
#include <math.h>

#define B_   4
#define C_   512
#define T_   32
#define HW_  1024
#define NCOL (T_*HW_)            // 32768 columns per batch
#define TOT  (B_*C_*T_*HW_)      // 67108864 elements

// Scratch (module-global device memory; allocated at load, not in kernel_launch)
__device__ float d_h[TOT];       // normalized input, layout [B,C,T,HW] (same as x)
__device__ float d_u[TOT];       // u  = A   * h   (A = Wq^T Wk)
__device__ float d_vp[TOT];      // v' = Wpv * h   (Wpv = Wproj Wv)
__device__ float d_W2[1024*512]; // rows [0,512)=A, rows [512,1024)=Wpv
__device__ float d_mean[B_*T_];
__device__ float d_rstd[B_*T_];

// ---------------------------------------------------------------------------
// Precompute W2 = [A ; Wpv].  A[i][j] = sum_o wq[o][i]*wk[o][j]
//                             Wpv[i][j] = sum_c wproj[i][c]*wv[c][j]
// grid: 2048 blocks x 256 threads (one output element per thread)
// ---------------------------------------------------------------------------
__global__ void prep_w2(const float* __restrict__ wq, const float* __restrict__ wk,
                        const float* __restrict__ wv, const float* __restrict__ wproj)
{
    int j = (blockIdx.x & 1) * 256 + threadIdx.x;   // 0..511
    int m = blockIdx.x >> 1;                        // 0..1023
    float acc = 0.f;
    if (m < 512) {
        #pragma unroll 4
        for (int o = 0; o < 512; o++)
            acc += wq[o*512 + m] * wk[o*512 + j];
    } else {
        int i = m - 512;
        #pragma unroll 4
        for (int c = 0; c < 512; c++)
            acc += wproj[i*512 + c] * wv[c*512 + j];
    }
    d_W2[m*512 + j] = acc;
}

// ---------------------------------------------------------------------------
// LayerNorm stats: one block per (b,t) group, reduce over C*HW = 524288 elems
// ---------------------------------------------------------------------------
__global__ void ln_stats(const float* __restrict__ x)
{
    int g = blockIdx.x;              // 0..127
    int b = g >> 5, t = g & 31;
    const float4* base = reinterpret_cast<const float4*>(
        x + ((size_t)(b * C_) * T_ + t) * HW_);
    float s = 0.f, ss = 0.f;
    for (int i = threadIdx.x; i < 512*256; i += blockDim.x) {
        int c = i >> 8, hw4 = i & 255;
        float4 v = base[(size_t)c * (T_*HW_/4) + hw4];
        s  += v.x + v.y + v.z + v.w;
        ss += v.x*v.x + v.y*v.y + v.z*v.z + v.w*v.w;
    }
    __shared__ float sm[64];
    #pragma unroll
    for (int o = 16; o > 0; o >>= 1) {
        s  += __shfl_down_sync(0xffffffffu, s,  o);
        ss += __shfl_down_sync(0xffffffffu, ss, o);
    }
    int w = threadIdx.x >> 5;
    if ((threadIdx.x & 31) == 0) { sm[w] = s; sm[32 + w] = ss; }
    __syncthreads();
    if (threadIdx.x == 0) {
        float S = 0.f, SS = 0.f;
        int nw = blockDim.x >> 5;
        for (int k = 0; k < nw; k++) { S += sm[k]; SS += sm[32 + k]; }
        float invn = 1.f / (float)(C_ * HW_);
        float m   = S * invn;
        float var = SS * invn - m * m;
        d_mean[g] = m;
        d_rstd[g] = rsqrtf(var + 1e-6f);
    }
}

// ---------------------------------------------------------------------------
// LayerNorm apply: h = (x - mean)*rstd*gamma + beta, float4 grid-stride
// ---------------------------------------------------------------------------
__global__ void ln_apply(const float* __restrict__ x,
                         const float* __restrict__ gamma,
                         const float* __restrict__ beta)
{
    size_t i4 = (size_t)blockIdx.x * blockDim.x + threadIdx.x;
    if (i4 >= (size_t)TOT/4) return;
    size_t i = i4 * 4;
    int t = (int)((i >> 10) & 31);
    int c = (int)((i >> 15) & 511);
    int b = (int)(i >> 24);
    int g = (b << 5) | t;
    float r  = d_rstd[g];
    float ga = gamma[c] * r;
    float be = beta[c] - d_mean[g] * ga;
    float4 v = reinterpret_cast<const float4*>(x)[i4];
    float4 o;
    o.x = v.x*ga + be; o.y = v.y*ga + be; o.z = v.z*ga + be; o.w = v.w*ga + be;
    reinterpret_cast<float4*>(d_h)[i4] = o;
}

// ---------------------------------------------------------------------------
// GEMM: [u ; vp] = W2[1024,512] * h_b[512,32768] per batch.
// 128x128x16 tiles, 256 threads, 8x8 microtile split as 4+4 fragments.
// ---------------------------------------------------------------------------
__global__ __launch_bounds__(256, 2) void gemm_uv()
{
    __shared__ float As[16][128];
    __shared__ float Bs[16][128];
    int b  = blockIdx.z;
    int m0 = blockIdx.y * 128;
    int n0 = blockIdx.x * 128;
    const float* hb = d_h + (size_t)b * C_ * NCOL;
    int tid = threadIdx.x;
    int tx = tid & 15, ty = tid >> 4;

    float acc[8][8];
    #pragma unroll
    for (int i = 0; i < 8; i++)
        #pragma unroll
        for (int j = 0; j < 8; j++) acc[i][j] = 0.f;

    for (int k0 = 0; k0 < 512; k0 += 16) {
        #pragma unroll
        for (int l = 0; l < 2; l++) {
            int a = l * 256 + tid;          // 0..511
            int row = a >> 2, kq = a & 3;   // A tile: 128 rows x 16 k
            float4 v = *reinterpret_cast<const float4*>(
                &d_W2[(size_t)(m0 + row) * 512 + k0 + kq*4]);
            As[kq*4+0][row] = v.x; As[kq*4+1][row] = v.y;
            As[kq*4+2][row] = v.z; As[kq*4+3][row] = v.w;
            int brow = a >> 5, bc = a & 31; // B tile: 16 rows x 128 n
            *reinterpret_cast<float4*>(&Bs[brow][bc*4]) =
                *reinterpret_cast<const float4*>(
                    &hb[(size_t)(k0 + brow) * NCOL + n0 + bc*4]);
        }
        __syncthreads();
        #pragma unroll
        for (int k = 0; k < 16; k++) {
            float ar[8], br[8];
            *reinterpret_cast<float4*>(ar)     = *reinterpret_cast<float4*>(&As[k][ty*4]);
            *reinterpret_cast<float4*>(ar + 4) = *reinterpret_cast<float4*>(&As[k][64 + ty*4]);
            *reinterpret_cast<float4*>(br)     = *reinterpret_cast<float4*>(&Bs[k][tx*4]);
            *reinterpret_cast<float4*>(br + 4) = *reinterpret_cast<float4*>(&Bs[k][64 + tx*4]);
            #pragma unroll
            for (int i = 0; i < 8; i++)
                #pragma unroll
                for (int j = 0; j < 8; j++)
                    acc[i][j] += ar[i] * br[j];
        }
        __syncthreads();
    }
    #pragma unroll
    for (int i = 0; i < 8; i++) {
        int m = m0 + ((i < 4) ? (ty*4 + i) : (64 + ty*4 + i - 4));
        float* dst = (m < 512) ? (d_u  + (size_t)(b*512 + m)       * NCOL)
                               : (d_vp + (size_t)(b*512 + m - 512) * NCOL);
        float4 w0 = make_float4(acc[i][0], acc[i][1], acc[i][2], acc[i][3]);
        float4 w1 = make_float4(acc[i][4], acc[i][5], acc[i][6], acc[i][7]);
        *reinterpret_cast<float4*>(&dst[n0 + tx*4])      = w0;
        *reinterpret_cast<float4*>(&dst[n0 + 64 + tx*4]) = w1;
    }
}

// ---------------------------------------------------------------------------
// Attention + residual: per block, 16 pixels (same b, consecutive hw).
//   logits[t,s,p] = sum_c h[c,t,p]*u[c,s,p] * C^-0.5   (causal softmax over s)
//   out[o,t,p]    = sum_s attn[t,s,p]*vp[o,s,p] + x[o,t,p]
// dynamic smem 96KB: [0,32K) chunkA / sL, [32K,64K) chunkB, [64K,96K) vp chunk
// ---------------------------------------------------------------------------
__global__ __launch_bounds__(256, 2) void attn_kernel(const float* __restrict__ x,
                                                      float* __restrict__ out)
{
    extern __shared__ float sm[];
    int blk = blockIdx.x;            // 0..255
    int b   = blk >> 6;              // 64 blocks per batch
    int hw0 = (blk & 63) * 16;
    int tid = threadIdx.x;
    int p = tid & 15, q = tid >> 4;
    int tt = q >> 2, ss = q & 3;
    const size_t pixbase = (size_t)b * C_ * T_ * HW_ + hw0;

    const float* hg = d_h + pixbase;
    const float* ug = d_u + pixbase;

    float acc[8][8];
    #pragma unroll
    for (int i = 0; i < 8; i++)
        #pragma unroll
        for (int j = 0; j < 8; j++) acc[i][j] = 0.f;

    // ---- phase 1: logits = h^T u (K=512 in chunks of 16 channels) ----
    for (int c0 = 0; c0 < 512; c0 += 16) {
        #pragma unroll 8
        for (int l = 0; l < 32; l++) {
            int j = l * 256 + tid;         // 0..8191 -> [c][t][p]
            int c = j >> 9, rem = j & 511;
            int t = rem >> 4, pl = rem & 15;
            size_t goff = ((size_t)(c0 + c) * T_ + t) * HW_ + pl;
            sm[j]        = hg[goff];
            sm[8192 + j] = ug[goff];
        }
        __syncthreads();
        #pragma unroll
        for (int c = 0; c < 16; c++) {
            float hv[8], uv[8];
            #pragma unroll
            for (int i = 0; i < 8; i++) hv[i] = sm[(c*32 + tt*8 + i)*16 + p];
            #pragma unroll
            for (int j = 0; j < 8; j++) uv[j] = sm[8192 + (c*32 + ss*8 + j)*16 + p];
            #pragma unroll
            for (int i = 0; i < 8; i++)
                #pragma unroll
                for (int j = 0; j < 8; j++)
                    acc[i][j] += hv[i] * uv[j];
        }
        __syncthreads();
    }

    // ---- phase 2: scaled logits -> sL [t][s][p] ----
    const float scale = 0.044194173824159216f;   // 512^-0.5
    #pragma unroll
    for (int i = 0; i < 8; i++)
        #pragma unroll
        for (int j = 0; j < 8; j++)
            sm[((tt*8 + i)*32 + ss*8 + j)*16 + p] = acc[i][j] * scale;
    __syncthreads();

    // ---- phase 3: causal softmax, each thread owns 2 (t,p) rows ----
    #pragma unroll
    for (int rr = 0; rr < 2; rr++) {
        int r = rr * 256 + tid;
        int t = r >> 4, pl = r & 15;
        float mx = -1e30f;
        for (int s = 0; s <= t; s++) mx = fmaxf(mx, sm[(t*32 + s)*16 + pl]);
        float Z = 0.f;
        for (int s = 0; s <= t; s++) Z += __expf(sm[(t*32 + s)*16 + pl] - mx);
        float iz = 1.f / Z;
        for (int s = 0; s < 32; s++) {
            float v = (s <= t) ? __expf(sm[(t*32 + s)*16 + pl] - mx) * iz : 0.f;
            sm[(t*32 + s)*16 + pl] = v;
        }
    }
    __syncthreads();

    // ---- phase 4: out = attn @ vp^T + x, o in chunks of 16 ----
    int oo = q & 3;
    for (int oc = 0; oc < 512; oc += 16) {
        #pragma unroll 8
        for (int l = 0; l < 32; l++) {        // FIXED: 32 iters = 8192 floats (16 o x 32 s x 16 p)
            int j = l * 256 + tid;            // 0..8191 -> [o][s][p]
            int o = j >> 9, rem = j & 511;
            int s = rem >> 4, pl = rem & 15;
            sm[16384 + j] = d_vp[pixbase + ((size_t)(oc + o) * T_ + s) * HW_ + pl];
        }
        __syncthreads();
        float acc2[8][4];
        #pragma unroll
        for (int i = 0; i < 8; i++)
            #pragma unroll
            for (int j = 0; j < 4; j++) acc2[i][j] = 0.f;
        #pragma unroll
        for (int s = 0; s < 32; s++) {
            float av[8], vv[4];
            #pragma unroll
            for (int i = 0; i < 8; i++) av[i] = sm[((tt*8 + i)*32 + s)*16 + p];
            #pragma unroll
            for (int j = 0; j < 4; j++) vv[j] = sm[16384 + ((oo*4 + j)*32 + s)*16 + p];
            #pragma unroll
            for (int i = 0; i < 8; i++)
                #pragma unroll
                for (int j = 0; j < 4; j++)
                    acc2[i][j] += av[i] * vv[j];
        }
        #pragma unroll
        for (int i = 0; i < 8; i++) {
            int t = tt*8 + i;
            #pragma unroll
            for (int j = 0; j < 4; j++) {
                int o = oc + oo*4 + j;
                size_t g = pixbase + ((size_t)o * T_ + t) * HW_ + p;
                out[g] = acc2[i][j] + x[g];
            }
        }
        __syncthreads();
    }
}

// ---------------------------------------------------------------------------
extern "C" void kernel_launch(void* const* d_in, const int* in_sizes, int n_in,
                              void* d_out, int out_size)
{
    const float* x     = (const float*)d_in[0];
    const float* gamma = (const float*)d_in[1];
    const float* beta  = (const float*)d_in[2];
    const float* wq    = (const float*)d_in[3];
    const float* wk    = (const float*)d_in[4];
    const float* wv    = (const float*)d_in[5];
    const float* wproj = (const float*)d_in[6];
    float* out = (float*)d_out;

    cudaFuncSetAttribute(attn_kernel, cudaFuncAttributeMaxDynamicSharedMemorySize, 98304);

    prep_w2<<<2048, 256>>>(wq, wk, wv, wproj);
    ln_stats<<<128, 512>>>(x);
    ln_apply<<<(TOT/4 + 255) / 256, 256>>>(x, gamma, beta);
    gemm_uv<<<dim3(NCOL/128, 1024/128, B_), 256>>>();
    attn_kernel<<<256, 256, 98304>>>(x, out);
}

// round 3
// speedup vs baseline: 2.2486x; 2.2486x over previous
#include <cuda_runtime.h>
#include <math.h>
#include <stdint.h>

#define B_   4
#define C_   512
#define T_   32
#define HW_  1024
#define NCOL (T_*HW_)            // 32768 columns per batch
#define TOT  (B_*C_*T_*HW_)      // 67108864 elements

// Scratch (module-global device memory)
__device__ float d_h[TOT];         // normalized input (tf32-rounded), [B,C,T,HW]
__device__ float d_u[TOT];         // u  = A   * h   (A = Wq^T Wk)
__device__ float d_vp[TOT];        // v' = Wpv * h   (Wpv = Wproj Wv)
__device__ float d_W2t[512*1024];  // transposed combined weights [k][m], tf32-rounded
__device__ float d_mean[B_*T_];
__device__ float d_rstd[B_*T_];

__device__ __forceinline__ float tf32r(float x) {
    uint32_t r;
    asm("cvt.rna.tf32.f32 %0, %1;" : "=r"(r) : "f"(x));
    return __uint_as_float(r);
}

__device__ __forceinline__ void cp16(float* dst, const float* src) {
    unsigned d = (unsigned)__cvta_generic_to_shared(dst);
    asm volatile("cp.async.cg.shared.global [%0], [%1], 16;\n" :: "r"(d), "l"(src));
}

#define MMA_TF32(d0,d1,d2,d3,a0,a1,a2,a3,b0,b1) \
    asm volatile("mma.sync.aligned.m16n8k8.row.col.f32.tf32.tf32.f32 " \
                 "{%0,%1,%2,%3},{%4,%5,%6,%7},{%8,%9},{%0,%1,%2,%3};" \
                 : "+f"(d0), "+f"(d1), "+f"(d2), "+f"(d3) \
                 : "r"(a0), "r"(a1), "r"(a2), "r"(a3), "r"(b0), "r"(b1))

// ---------------------------------------------------------------------------
// Precompute W2t[j][m] (tf32): m<512: A[m][j]=sum_o wq[o,m]wk[o,j]
//                              m>=512: Wpv[m-512][j]=sum_c wproj[m-512,c]wv[c,j]
// ---------------------------------------------------------------------------
__global__ void prep_w2(const float* __restrict__ wq, const float* __restrict__ wk,
                        const float* __restrict__ wv, const float* __restrict__ wproj)
{
    int j = (blockIdx.x & 1) * 256 + threadIdx.x;   // 0..511  (input channel = k)
    int m = blockIdx.x >> 1;                        // 0..1023
    float acc = 0.f;
    if (m < 512) {
        #pragma unroll 4
        for (int o = 0; o < 512; o++)
            acc += wq[o*512 + m] * wk[o*512 + j];
    } else {
        int i = m - 512;
        #pragma unroll 4
        for (int c = 0; c < 512; c++)
            acc += wproj[i*512 + c] * wv[c*512 + j];
    }
    d_W2t[(size_t)j * 1024 + m] = tf32r(acc);
}

// ---------------------------------------------------------------------------
// LayerNorm stats: one block per (b,t) group, reduce over C*HW
// ---------------------------------------------------------------------------
__global__ void ln_stats(const float* __restrict__ x)
{
    int g = blockIdx.x;              // 0..127
    int b = g >> 5, t = g & 31;
    const float4* base = reinterpret_cast<const float4*>(
        x + ((size_t)(b * C_) * T_ + t) * HW_);
    float s = 0.f, ss = 0.f;
    for (int i = threadIdx.x; i < 512*256; i += blockDim.x) {
        int c = i >> 8, hw4 = i & 255;
        float4 v = base[(size_t)c * (T_*HW_/4) + hw4];
        s  += v.x + v.y + v.z + v.w;
        ss += v.x*v.x + v.y*v.y + v.z*v.z + v.w*v.w;
    }
    __shared__ float sm[64];
    #pragma unroll
    for (int o = 16; o > 0; o >>= 1) {
        s  += __shfl_down_sync(0xffffffffu, s,  o);
        ss += __shfl_down_sync(0xffffffffu, ss, o);
    }
    int w = threadIdx.x >> 5;
    if ((threadIdx.x & 31) == 0) { sm[w] = s; sm[32 + w] = ss; }
    __syncthreads();
    if (threadIdx.x == 0) {
        float S = 0.f, SS = 0.f;
        int nw = blockDim.x >> 5;
        for (int k = 0; k < nw; k++) { S += sm[k]; SS += sm[32 + k]; }
        float invn = 1.f / (float)(C_ * HW_);
        float m   = S * invn;
        float var = SS * invn - m * m;
        d_mean[g] = m;
        d_rstd[g] = rsqrtf(var + 1e-6f);
    }
}

// ---------------------------------------------------------------------------
// LayerNorm apply: h = tf32((x - mean)*rstd*gamma + beta)
// ---------------------------------------------------------------------------
__global__ void ln_apply(const float* __restrict__ x,
                         const float* __restrict__ gamma,
                         const float* __restrict__ beta)
{
    size_t i4 = (size_t)blockIdx.x * blockDim.x + threadIdx.x;
    if (i4 >= (size_t)TOT/4) return;
    size_t i = i4 * 4;
    int t = (int)((i >> 10) & 31);
    int c = (int)((i >> 15) & 511);
    int b = (int)(i >> 24);
    int g = (b << 5) | t;
    float r  = d_rstd[g];
    float ga = gamma[c] * r;
    float be = beta[c] - d_mean[g] * ga;
    float4 v = reinterpret_cast<const float4*>(x)[i4];
    float4 o;
    o.x = tf32r(v.x*ga + be); o.y = tf32r(v.y*ga + be);
    o.z = tf32r(v.z*ga + be); o.w = tf32r(v.w*ga + be);
    reinterpret_cast<float4*>(d_h)[i4] = o;
}

// ---------------------------------------------------------------------------
// Tensor-core GEMM: [u ; vp] = W2[1024,512] * h_b[512,32768] per batch.
// tf32 mma.sync m16n8k8. Block 128x128x32, 8 warps (2x4), warp tile 64x32.
// Double-buffered smem via cp.async. smem rows padded to 136 words.
// ---------------------------------------------------------------------------
#define SROW 136                     // 128 + 8 pad (words)
#define TILE_W (32*SROW)             // 4352 words per tile
#define BUF_W  (2*TILE_W)            // As+Bs per buffer

__global__ __launch_bounds__(256, 2) void gemm_uv_tc()
{
    extern __shared__ float smem[];  // [2][As 32x136 | Bs 32x136] = 69632 B
    int b  = blockIdx.z;
    int m0 = blockIdx.x * 128;       // m fastest -> 8 m-tiles share B tile in L2
    int n0 = blockIdx.y * 128;
    const float* hb = d_h + (size_t)b * C_ * NCOL;
    int tid  = threadIdx.x;
    int lane = tid & 31;
    int w    = tid >> 5;
    int warpM = w >> 2, warpN = w & 3;
    int g = lane >> 2, tq = lane & 3;
    int am = warpM * 64 + g;         // A fragment base row within tile
    int bn = warpN * 32 + g;         // B fragment base col within tile

    float acc[4][4][4];
    #pragma unroll
    for (int i = 0; i < 4; i++)
        #pragma unroll
        for (int j = 0; j < 4; j++)
            #pragma unroll
            for (int r = 0; r < 4; r++) acc[i][j][r] = 0.f;

    // tile loader: 8 cp.async(16B) per thread
    auto load_tile = [&](int k0, int buf) {
        float* As = smem + buf * BUF_W;
        float* Bs = As + TILE_W;
        #pragma unroll
        for (int r = 0; r < 4; r++) {
            int chunk = r * 256 + tid;          // 0..1023
            int k  = chunk >> 5;
            int c4 = (chunk & 31) * 4;
            cp16(&As[k * SROW + c4], &d_W2t[(size_t)(k0 + k) * 1024 + m0 + c4]);
            cp16(&Bs[k * SROW + c4], &hb[(size_t)(k0 + k) * NCOL + n0 + c4]);
        }
    };

    load_tile(0, 0);
    asm volatile("cp.async.commit_group;\n");

    for (int it = 0; it < 16; it++) {
        if (it < 15) {
            load_tile((it + 1) * 32, (it + 1) & 1);
            asm volatile("cp.async.commit_group;\n");
            asm volatile("cp.async.wait_group 1;\n");
        } else {
            asm volatile("cp.async.wait_group 0;\n");
        }
        __syncthreads();

        const uint32_t* As = reinterpret_cast<const uint32_t*>(smem + (it & 1) * BUF_W);
        const uint32_t* Bs = As + TILE_W;

        #pragma unroll
        for (int kk = 0; kk < 32; kk += 8) {
            uint32_t a[4][4], bq[4][2];
            #pragma unroll
            for (int mf = 0; mf < 4; mf++) {
                int row = am + mf * 16;
                a[mf][0] = As[(kk + tq)     * SROW + row];
                a[mf][1] = As[(kk + tq)     * SROW + row + 8];
                a[mf][2] = As[(kk + tq + 4) * SROW + row];
                a[mf][3] = As[(kk + tq + 4) * SROW + row + 8];
            }
            #pragma unroll
            for (int nf = 0; nf < 4; nf++) {
                int col = bn + nf * 8;
                bq[nf][0] = Bs[(kk + tq)     * SROW + col];
                bq[nf][1] = Bs[(kk + tq + 4) * SROW + col];
            }
            #pragma unroll
            for (int mf = 0; mf < 4; mf++)
                #pragma unroll
                for (int nf = 0; nf < 4; nf++)
                    MMA_TF32(acc[mf][nf][0], acc[mf][nf][1], acc[mf][nf][2], acc[mf][nf][3],
                             a[mf][0], a[mf][1], a[mf][2], a[mf][3],
                             bq[nf][0], bq[nf][1]);
        }
        __syncthreads();
    }

    // epilogue
    bool isU = (m0 < 512);
    float* outbase = isU ? (d_u  + (size_t)(b * 512 + m0)       * NCOL)
                         : (d_vp + (size_t)(b * 512 + m0 - 512) * NCOL);
    #pragma unroll
    for (int mf = 0; mf < 4; mf++) {
        int mrow = warpM * 64 + mf * 16 + g;   // within tile
        #pragma unroll
        for (int nf = 0; nf < 4; nf++) {
            int ncol = n0 + warpN * 32 + nf * 8 + tq * 2;
            float2 lo = make_float2(acc[mf][nf][0], acc[mf][nf][1]);
            float2 hi = make_float2(acc[mf][nf][2], acc[mf][nf][3]);
            *reinterpret_cast<float2*>(outbase + (size_t)mrow * NCOL + ncol)       = lo;
            *reinterpret_cast<float2*>(outbase + (size_t)(mrow + 8) * NCOL + ncol) = hi;
        }
    }
}

// ---------------------------------------------------------------------------
// Attention + residual (unchanged from R2)
// ---------------------------------------------------------------------------
__global__ __launch_bounds__(256, 2) void attn_kernel(const float* __restrict__ x,
                                                      float* __restrict__ out)
{
    extern __shared__ float sm[];
    int blk = blockIdx.x;            // 0..255
    int b   = blk >> 6;
    int hw0 = (blk & 63) * 16;
    int tid = threadIdx.x;
    int p = tid & 15, q = tid >> 4;
    int tt = q >> 2, ss = q & 3;
    const size_t pixbase = (size_t)b * C_ * T_ * HW_ + hw0;

    const float* hg = d_h + pixbase;
    const float* ug = d_u + pixbase;

    float acc[8][8];
    #pragma unroll
    for (int i = 0; i < 8; i++)
        #pragma unroll
        for (int j = 0; j < 8; j++) acc[i][j] = 0.f;

    for (int c0 = 0; c0 < 512; c0 += 16) {
        #pragma unroll 8
        for (int l = 0; l < 32; l++) {
            int j = l * 256 + tid;
            int c = j >> 9, rem = j & 511;
            int t = rem >> 4, pl = rem & 15;
            size_t goff = ((size_t)(c0 + c) * T_ + t) * HW_ + pl;
            sm[j]        = hg[goff];
            sm[8192 + j] = ug[goff];
        }
        __syncthreads();
        #pragma unroll
        for (int c = 0; c < 16; c++) {
            float hv[8], uv[8];
            #pragma unroll
            for (int i = 0; i < 8; i++) hv[i] = sm[(c*32 + tt*8 + i)*16 + p];
            #pragma unroll
            for (int j = 0; j < 8; j++) uv[j] = sm[8192 + (c*32 + ss*8 + j)*16 + p];
            #pragma unroll
            for (int i = 0; i < 8; i++)
                #pragma unroll
                for (int j = 0; j < 8; j++)
                    acc[i][j] += hv[i] * uv[j];
        }
        __syncthreads();
    }

    const float scale = 0.044194173824159216f;   // 512^-0.5
    #pragma unroll
    for (int i = 0; i < 8; i++)
        #pragma unroll
        for (int j = 0; j < 8; j++)
            sm[((tt*8 + i)*32 + ss*8 + j)*16 + p] = acc[i][j] * scale;
    __syncthreads();

    #pragma unroll
    for (int rr = 0; rr < 2; rr++) {
        int r = rr * 256 + tid;
        int t = r >> 4, pl = r & 15;
        float mx = -1e30f;
        for (int s = 0; s <= t; s++) mx = fmaxf(mx, sm[(t*32 + s)*16 + pl]);
        float Z = 0.f;
        for (int s = 0; s <= t; s++) Z += __expf(sm[(t*32 + s)*16 + pl] - mx);
        float iz = 1.f / Z;
        for (int s = 0; s < 32; s++) {
            float v = (s <= t) ? __expf(sm[(t*32 + s)*16 + pl] - mx) * iz : 0.f;
            sm[(t*32 + s)*16 + pl] = v;
        }
    }
    __syncthreads();

    int oo = q & 3;
    for (int oc = 0; oc < 512; oc += 16) {
        #pragma unroll 8
        for (int l = 0; l < 32; l++) {
            int j = l * 256 + tid;
            int o = j >> 9, rem = j & 511;
            int s = rem >> 4, pl = rem & 15;
            sm[16384 + j] = d_vp[pixbase + ((size_t)(oc + o) * T_ + s) * HW_ + pl];
        }
        __syncthreads();
        float acc2[8][4];
        #pragma unroll
        for (int i = 0; i < 8; i++)
            #pragma unroll
            for (int j = 0; j < 4; j++) acc2[i][j] = 0.f;
        #pragma unroll
        for (int s = 0; s < 32; s++) {
            float av[8], vv[4];
            #pragma unroll
            for (int i = 0; i < 8; i++) av[i] = sm[((tt*8 + i)*32 + s)*16 + p];
            #pragma unroll
            for (int j = 0; j < 4; j++) vv[j] = sm[16384 + ((oo*4 + j)*32 + s)*16 + p];
            #pragma unroll
            for (int i = 0; i < 8; i++)
                #pragma unroll
                for (int j = 0; j < 4; j++)
                    acc2[i][j] += av[i] * vv[j];
        }
        #pragma unroll
        for (int i = 0; i < 8; i++) {
            int t = tt*8 + i;
            #pragma unroll
            for (int j = 0; j < 4; j++) {
                int o = oc + oo*4 + j;
                size_t gg = pixbase + ((size_t)o * T_ + t) * HW_ + p;
                out[gg] = acc2[i][j] + x[gg];
            }
        }
        __syncthreads();
    }
}

// ---------------------------------------------------------------------------
extern "C" void kernel_launch(void* const* d_in, const int* in_sizes, int n_in,
                              void* d_out, int out_size)
{
    const float* x     = (const float*)d_in[0];
    const float* gamma = (const float*)d_in[1];
    const float* beta  = (const float*)d_in[2];
    const float* wq    = (const float*)d_in[3];
    const float* wk    = (const float*)d_in[4];
    const float* wv    = (const float*)d_in[5];
    const float* wproj = (const float*)d_in[6];
    float* out = (float*)d_out;

    cudaFuncSetAttribute(attn_kernel, cudaFuncAttributeMaxDynamicSharedMemorySize, 98304);
    cudaFuncSetAttribute(gemm_uv_tc, cudaFuncAttributeMaxDynamicSharedMemorySize, 69632);

    prep_w2<<<2048, 256>>>(wq, wk, wv, wproj);
    ln_stats<<<128, 512>>>(x);
    ln_apply<<<(TOT/4 + 255) / 256, 256>>>(x, gamma, beta);
    gemm_uv_tc<<<dim3(8, 256, B_), 256, 69632>>>();
    attn_kernel<<<256, 256, 98304>>>(x, out);
}

// round 5
// speedup vs baseline: 2.3757x; 1.0565x over previous
#include <cuda_runtime.h>
#include <math.h>
#include <stdint.h>

#define B_   4
#define C_   512
#define T_   32
#define HW_  1024
#define NCOL (T_*HW_)            // 32768 columns per batch
#define TOT  (B_*C_*T_*HW_)

// Scratch
__device__ float d_h[TOT];         // normalized input (tf32-rounded), [B,C,T,HW]
__device__ float d_u[TOT];         // u  = A   * h  (tf32-rounded)
__device__ float d_vp[TOT];        // v' = Wpv * h  (tf32-rounded)
__device__ float d_W2t[512*1024];  // combined weights [k][m], tf32-rounded
__device__ float d_mean[B_*T_];
__device__ float d_rstd[B_*T_];

__device__ __forceinline__ float tf32r(float x) {
    uint32_t r;
    asm("cvt.rna.tf32.f32 %0, %1;" : "=r"(r) : "f"(x));
    return __uint_as_float(r);
}

__device__ __forceinline__ void cp16(float* dst, const float* src) {
    unsigned d = (unsigned)__cvta_generic_to_shared(dst);
    asm volatile("cp.async.cg.shared.global [%0], [%1], 16;\n" :: "r"(d), "l"(src));
}

#define MMA_TF32(d0,d1,d2,d3,a0,a1,a2,a3,b0,b1) \
    asm volatile("mma.sync.aligned.m16n8k8.row.col.f32.tf32.tf32.f32 " \
                 "{%0,%1,%2,%3},{%4,%5,%6,%7},{%8,%9},{%0,%1,%2,%3};" \
                 : "+f"(d0), "+f"(d1), "+f"(d2), "+f"(d3) \
                 : "r"(a0), "r"(a1), "r"(a2), "r"(a3), "r"(b0), "r"(b1))

// ---------------------------------------------------------------------------
// prep_w2: W2t[k][m] tf32.  m<512: A[m][k]; m>=512: Wpv[m-512][k]
// ---------------------------------------------------------------------------
__global__ void prep_w2(const float* __restrict__ wq, const float* __restrict__ wk,
                        const float* __restrict__ wv, const float* __restrict__ wproj)
{
    int j = (blockIdx.x & 1) * 256 + threadIdx.x;   // k index
    int m = blockIdx.x >> 1;
    float acc = 0.f;
    if (m < 512) {
        #pragma unroll 4
        for (int o = 0; o < 512; o++)
            acc += wq[o*512 + m] * wk[o*512 + j];
    } else {
        int i = m - 512;
        #pragma unroll 4
        for (int c = 0; c < 512; c++)
            acc += wproj[i*512 + c] * wv[c*512 + j];
    }
    d_W2t[(size_t)j * 1024 + m] = tf32r(acc);
}

// ---------------------------------------------------------------------------
// LayerNorm stats
// ---------------------------------------------------------------------------
__global__ void ln_stats(const float* __restrict__ x)
{
    int g = blockIdx.x;
    int b = g >> 5, t = g & 31;
    const float4* base = reinterpret_cast<const float4*>(
        x + ((size_t)(b * C_) * T_ + t) * HW_);
    float s = 0.f, ss = 0.f;
    for (int i = threadIdx.x; i < 512*256; i += blockDim.x) {
        int c = i >> 8, hw4 = i & 255;
        float4 v = base[(size_t)c * (T_*HW_/4) + hw4];
        s  += v.x + v.y + v.z + v.w;
        ss += v.x*v.x + v.y*v.y + v.z*v.z + v.w*v.w;
    }
    __shared__ float sm[64];
    #pragma unroll
    for (int o = 16; o > 0; o >>= 1) {
        s  += __shfl_down_sync(0xffffffffu, s,  o);
        ss += __shfl_down_sync(0xffffffffu, ss, o);
    }
    int w = threadIdx.x >> 5;
    if ((threadIdx.x & 31) == 0) { sm[w] = s; sm[32 + w] = ss; }
    __syncthreads();
    if (threadIdx.x == 0) {
        float S = 0.f, SS = 0.f;
        int nw = blockDim.x >> 5;
        for (int k = 0; k < nw; k++) { S += sm[k]; SS += sm[32 + k]; }
        float invn = 1.f / (float)(C_ * HW_);
        float m   = S * invn;
        float var = SS * invn - m * m;
        d_mean[g] = m;
        d_rstd[g] = rsqrtf(var + 1e-6f);
    }
}

// ---------------------------------------------------------------------------
// LayerNorm apply -> tf32-rounded h
// ---------------------------------------------------------------------------
__global__ void ln_apply(const float* __restrict__ x,
                         const float* __restrict__ gamma,
                         const float* __restrict__ beta)
{
    size_t i4 = (size_t)blockIdx.x * blockDim.x + threadIdx.x;
    if (i4 >= (size_t)TOT/4) return;
    size_t i = i4 * 4;
    int t = (int)((i >> 10) & 31);
    int c = (int)((i >> 15) & 511);
    int b = (int)(i >> 24);
    int g = (b << 5) | t;
    float r  = d_rstd[g];
    float ga = gamma[c] * r;
    float be = beta[c] - d_mean[g] * ga;
    float4 v = reinterpret_cast<const float4*>(x)[i4];
    float4 o;
    o.x = tf32r(v.x*ga + be); o.y = tf32r(v.y*ga + be);
    o.z = tf32r(v.z*ga + be); o.w = tf32r(v.w*ga + be);
    reinterpret_cast<float4*>(d_h)[i4] = o;
}

// ---------------------------------------------------------------------------
// GEMM: [u;vp] = W2(1024x512) * h(512x32768) per batch. mma.sync tf32.
// Block 128x128, 8 warps (2x4), warp tile 64x32. 4-stage cp.async, k=16/stage.
// ---------------------------------------------------------------------------
#define SROW 136                 // 128 + 8 pad words
#define STW  (16*SROW)           // 2176 words per A or B stage tile
#define SBUF (2*STW)             // 4352 words per stage

__global__ __launch_bounds__(256, 2) void gemm_uv_tc()
{
    extern __shared__ float smem[];  // 4 stages * 4352 words = 69632 B
    int b  = blockIdx.z;
    int m0 = blockIdx.x * 128;       // m fastest -> B tile L2 reuse
    int n0 = blockIdx.y * 128;
    const float* hb = d_h + (size_t)b * C_ * NCOL;
    int tid  = threadIdx.x;
    int lane = tid & 31;
    int w    = tid >> 5;
    int warpM = w >> 2, warpN = w & 3;
    int g = lane >> 2, tq = lane & 3;
    int am = warpM * 64 + g;
    int bn = warpN * 32 + g;

    float acc[4][4][4];
    #pragma unroll
    for (int i = 0; i < 4; i++)
        #pragma unroll
        for (int j = 0; j < 4; j++)
            #pragma unroll
            for (int r = 0; r < 4; r++) acc[i][j][r] = 0.f;

    auto load_stage = [&](int k0, int buf) {
        float* As = smem + buf * SBUF;
        float* Bs = As + STW;
        #pragma unroll
        for (int r = 0; r < 2; r++) {
            int ch = r * 256 + tid;          // 0..511
            int k  = ch >> 5;
            int c4 = (ch & 31) * 4;
            cp16(&As[k * SROW + c4], &d_W2t[(size_t)(k0 + k) * 1024 + m0 + c4]);
            cp16(&Bs[k * SROW + c4], &hb[(size_t)(k0 + k) * NCOL + n0 + c4]);
        }
    };

    #pragma unroll
    for (int p = 0; p < 3; p++) {
        load_stage(p * 16, p);
        asm volatile("cp.async.commit_group;\n");
    }

    for (int it = 0; it < 32; it++) {
        asm volatile("cp.async.wait_group 2;\n");
        __syncthreads();

        const uint32_t* As = reinterpret_cast<const uint32_t*>(smem + (it & 3) * SBUF);
        const uint32_t* Bs = As + STW;

        #pragma unroll
        for (int kk = 0; kk < 16; kk += 8) {
            uint32_t a[4][4], bq[4][2];
            #pragma unroll
            for (int mf = 0; mf < 4; mf++) {
                int row = am + mf * 16;
                a[mf][0] = As[(kk + tq)     * SROW + row];
                a[mf][1] = As[(kk + tq)     * SROW + row + 8];
                a[mf][2] = As[(kk + tq + 4) * SROW + row];
                a[mf][3] = As[(kk + tq + 4) * SROW + row + 8];
            }
            #pragma unroll
            for (int nf = 0; nf < 4; nf++) {
                int col = bn + nf * 8;
                bq[nf][0] = Bs[(kk + tq)     * SROW + col];
                bq[nf][1] = Bs[(kk + tq + 4) * SROW + col];
            }
            #pragma unroll
            for (int mf = 0; mf < 4; mf++)
                #pragma unroll
                for (int nf = 0; nf < 4; nf++)
                    MMA_TF32(acc[mf][nf][0], acc[mf][nf][1], acc[mf][nf][2], acc[mf][nf][3],
                             a[mf][0], a[mf][1], a[mf][2], a[mf][3],
                             bq[nf][0], bq[nf][1]);
        }
        if (it + 3 < 32)
            load_stage((it + 3) * 16, (it + 3) & 3);
        asm volatile("cp.async.commit_group;\n");
    }

    // epilogue (tf32-rounded: consumed by tensor-core attention)
    bool isU = (m0 < 512);
    float* outbase = isU ? (d_u  + (size_t)(b * 512 + m0)       * NCOL)
                         : (d_vp + (size_t)(b * 512 + m0 - 512) * NCOL);
    #pragma unroll
    for (int mf = 0; mf < 4; mf++) {
        int mrow = warpM * 64 + mf * 16 + g;
        #pragma unroll
        for (int nf = 0; nf < 4; nf++) {
            int ncol = n0 + warpN * 32 + nf * 8 + tq * 2;
            float2 lo = make_float2(tf32r(acc[mf][nf][0]), tf32r(acc[mf][nf][1]));
            float2 hi = make_float2(tf32r(acc[mf][nf][2]), tf32r(acc[mf][nf][3]));
            *reinterpret_cast<float2*>(outbase + (size_t)mrow * NCOL + ncol)       = lo;
            *reinterpret_cast<float2*>(outbase + (size_t)(mrow + 8) * NCOL + ncol) = hi;
        }
    }
}

// ---------------------------------------------------------------------------
// Tensor-core attention + residual. Block = 8 pixels, 8 warps (warp = pixel).
// Phase1: G[t][s] = sum_c H[c][t]U[c][s]  (mma, k=512 in 16-chunks)
// softmax (causal), Phase4: out[o][t] = sum_s G[t][s] vp[o][s]  (mma, k=32)
// SMEM layouts (pixel-last, bank-engineered strides):
//   Hs/Us [c16][t32*9][px8]  c-stride 296   (phase1; aliased by Gs after)
//   Gs    [t32][s32*9][px8]  t-stride 292
//   VPs   [s32][o16*9][px8]  s-stride 168
//   Os    [t32][o16*10][px8] t-stride 164
// ---------------------------------------------------------------------------
#define HS_CSTR 296
#define GS_TSTR 292
#define VP_SSTR 168
#define OS_TSTR 164
#define ATTN_SMEM_FLOATS (9344 + 5376 + 5248)   // Gs + VPs + Os = 19968

__global__ __launch_bounds__(256, 2) void attn_mma(const float* __restrict__ x,
                                                   float* __restrict__ out)
{
    extern __shared__ float sm[];
    float* Hs  = sm;                 // 16*296 = 4736 (phase1)
    float* Us  = sm + 4736;          // 4736          (phase1)
    float* Gs  = sm;                 // 32*292 = 9344 (aliases Hs/Us)
    float* VPs = sm + 9344;          // 32*168 = 5376
    float* Os  = sm + 14720;         // 32*164 = 5248

    int blk = blockIdx.x;            // 0..511
    int b   = blk >> 7;
    int hw0 = (blk & 127) * 8;
    int tid  = threadIdx.x;
    int lane = tid & 31;
    int px   = tid >> 5;             // warp = pixel 0..7
    int g = lane >> 2, tq = lane & 3;
    const size_t pixbase = (size_t)b * C_ * T_ * HW_ + hw0;
    const float* hg = d_h  + pixbase;
    const float* ug = d_u  + pixbase;
    const float* vg = d_vp + pixbase;

    // ---------------- phase 1: logits ----------------
    float acc1[2][4][4];
    #pragma unroll
    for (int i = 0; i < 2; i++)
        #pragma unroll
        for (int j = 0; j < 4; j++)
            #pragma unroll
            for (int r = 0; r < 4; r++) acc1[i][j][r] = 0.f;

    for (int c0 = 0; c0 < 512; c0 += 16) {
        #pragma unroll
        for (int it2 = 0; it2 < 8; it2++) {
            int flat = it2 * 256 + tid;          // float2 units, 0..2047
            int pp = flat & 3;
            int t  = (flat >> 2) & 31;
            int c  = flat >> 7;                  // 0..15
            size_t go = ((size_t)(c0 + c) * 32 + t) * 1024 + pp * 2;
            float2 hv = *reinterpret_cast<const float2*>(hg + go);
            float2 uv = *reinterpret_cast<const float2*>(ug + go);
            int so = c * HS_CSTR + t * 9 + pp * 2;
            Hs[so] = hv.x; Hs[so + 1] = hv.y;
            Us[so] = uv.x; Us[so + 1] = uv.y;
        }
        __syncthreads();

        const uint32_t* Hu = reinterpret_cast<const uint32_t*>(Hs);
        const uint32_t* Uu = reinterpret_cast<const uint32_t*>(Us);
        #pragma unroll
        for (int kk = 0; kk < 16; kk += 8) {
            uint32_t a[2][4], bq[4][2];
            #pragma unroll
            for (int mf = 0; mf < 2; mf++) {
                int base = (kk + tq) * HS_CSTR + (mf * 16 + g) * 9 + px;
                a[mf][0] = Hu[base];
                a[mf][1] = Hu[base + 72];                        // t+8
                a[mf][2] = Hu[base + 4 * HS_CSTR];               // k+4
                a[mf][3] = Hu[base + 4 * HS_CSTR + 72];
            }
            #pragma unroll
            for (int nf = 0; nf < 4; nf++) {
                int base = (kk + tq) * HS_CSTR + (nf * 8 + g) * 9 + px;
                bq[nf][0] = Uu[base];
                bq[nf][1] = Uu[base + 4 * HS_CSTR];
            }
            #pragma unroll
            for (int mf = 0; mf < 2; mf++)
                #pragma unroll
                for (int nf = 0; nf < 4; nf++)
                    MMA_TF32(acc1[mf][nf][0], acc1[mf][nf][1], acc1[mf][nf][2], acc1[mf][nf][3],
                             a[mf][0], a[mf][1], a[mf][2], a[mf][3],
                             bq[nf][0], bq[nf][1]);
        }
        __syncthreads();
    }

    // write scaled logits into Gs
    const float scale = 0.044194173824159216f;   // 512^-0.5
    #pragma unroll
    for (int mf = 0; mf < 2; mf++) {
        #pragma unroll
        for (int nf = 0; nf < 4; nf++) {
            int t = mf * 16 + g;
            int s = nf * 8 + tq * 2;
            Gs[t * GS_TSTR + s * 9 + px]             = acc1[mf][nf][0] * scale;
            Gs[t * GS_TSTR + (s + 1) * 9 + px]       = acc1[mf][nf][1] * scale;
            Gs[(t + 8) * GS_TSTR + s * 9 + px]       = acc1[mf][nf][2] * scale;
            Gs[(t + 8) * GS_TSTR + (s + 1) * 9 + px] = acc1[mf][nf][3] * scale;
        }
    }
    __syncthreads();

    // ---------------- causal softmax (thread = (px_s, t) row) ----------------
    {
        int px_s = tid & 7;
        int t    = tid >> 3;
        int base = t * GS_TSTR + px_s;
        float mx = -1e30f;
        for (int s = 0; s <= t; s++) mx = fmaxf(mx, Gs[base + s * 9]);
        float Z = 0.f;
        for (int s = 0; s <= t; s++) Z += __expf(Gs[base + s * 9] - mx);
        float iz = 1.f / Z;
        for (int s = 0; s < 32; s++) {
            float v = (s <= t) ? __expf(Gs[base + s * 9] - mx) * iz : 0.f;
            Gs[base + s * 9] = tf32r(v);
        }
    }
    __syncthreads();

    // ---------------- phase 4: out = G @ vp^T + x ----------------
    const uint32_t* Gu = reinterpret_cast<const uint32_t*>(Gs);
    for (int oc = 0; oc < 512; oc += 16) {
        #pragma unroll
        for (int it2 = 0; it2 < 8; it2++) {
            int flat = it2 * 256 + tid;
            int pp = flat & 3;
            int s  = (flat >> 2) & 31;
            int o  = flat >> 7;                  // 0..15
            size_t go = ((size_t)(oc + o) * 32 + s) * 1024 + pp * 2;
            float2 v = *reinterpret_cast<const float2*>(vg + go);
            int so = s * VP_SSTR + o * 9 + pp * 2;
            VPs[so] = v.x; VPs[so + 1] = v.y;
        }
        __syncthreads();

        float acc2[2][2][4];
        #pragma unroll
        for (int i = 0; i < 2; i++)
            #pragma unroll
            for (int j = 0; j < 2; j++)
                #pragma unroll
                for (int r = 0; r < 4; r++) acc2[i][j][r] = 0.f;

        const uint32_t* Vu = reinterpret_cast<const uint32_t*>(VPs);
        #pragma unroll
        for (int kk = 0; kk < 32; kk += 8) {
            uint32_t a[2][4], bq[2][2];
            #pragma unroll
            for (int mf = 0; mf < 2; mf++) {
                int base = (mf * 16 + g) * GS_TSTR + (kk + tq) * 9 + px;
                a[mf][0] = Gu[base];
                a[mf][1] = Gu[base + 8 * GS_TSTR];   // t+8
                a[mf][2] = Gu[base + 36];            // k+4
                a[mf][3] = Gu[base + 8 * GS_TSTR + 36];
            }
            #pragma unroll
            for (int nf = 0; nf < 2; nf++) {
                int base = (kk + tq) * VP_SSTR + (nf * 8 + g) * 9 + px;
                bq[nf][0] = Vu[base];
                bq[nf][1] = Vu[base + 4 * VP_SSTR];
            }
            #pragma unroll
            for (int mf = 0; mf < 2; mf++)
                #pragma unroll
                for (int nf = 0; nf < 2; nf++)
                    MMA_TF32(acc2[mf][nf][0], acc2[mf][nf][1], acc2[mf][nf][2], acc2[mf][nf][3],
                             a[mf][0], a[mf][1], a[mf][2], a[mf][3],
                             bq[nf][0], bq[nf][1]);
        }

        // frags -> Os
        #pragma unroll
        for (int mf = 0; mf < 2; mf++) {
            #pragma unroll
            for (int nf = 0; nf < 2; nf++) {
                int t = mf * 16 + g;
                int o = nf * 8 + tq * 2;
                Os[t * OS_TSTR + o * 10 + px]             = acc2[mf][nf][0];
                Os[t * OS_TSTR + (o + 1) * 10 + px]       = acc2[mf][nf][1];
                Os[(t + 8) * OS_TSTR + o * 10 + px]       = acc2[mf][nf][2];
                Os[(t + 8) * OS_TSTR + (o + 1) * 10 + px] = acc2[mf][nf][3];
            }
        }
        __syncthreads();

        // Os + x -> out (coalesced)
        #pragma unroll
        for (int it2 = 0; it2 < 8; it2++) {
            int flat = it2 * 256 + tid;
            int pp = flat & 3;
            int t  = (flat >> 2) & 31;
            int o  = flat >> 7;
            size_t gg = pixbase + ((size_t)(oc + o) * 32 + t) * 1024 + pp * 2;
            float2 xv = *reinterpret_cast<const float2*>(x + gg);
            int so = t * OS_TSTR + o * 10 + pp * 2;
            float2 ov;
            ov.x = Os[so]     + xv.x;
            ov.y = Os[so + 1] + xv.y;
            *reinterpret_cast<float2*>(out + gg) = ov;
        }
        __syncthreads();
    }
}

// ---------------------------------------------------------------------------
extern "C" void kernel_launch(void* const* d_in, const int* in_sizes, int n_in,
                              void* d_out, int out_size)
{
    const float* x     = (const float*)d_in[0];
    const float* gamma = (const float*)d_in[1];
    const float* beta  = (const float*)d_in[2];
    const float* wq    = (const float*)d_in[3];
    const float* wk    = (const float*)d_in[4];
    const float* wv    = (const float*)d_in[5];
    const float* wproj = (const float*)d_in[6];
    float* out = (float*)d_out;

    cudaFuncSetAttribute(gemm_uv_tc, cudaFuncAttributeMaxDynamicSharedMemorySize,
                         4 * SBUF * 4);
    cudaFuncSetAttribute(attn_mma, cudaFuncAttributeMaxDynamicSharedMemorySize,
                         ATTN_SMEM_FLOATS * 4);

    prep_w2<<<2048, 256>>>(wq, wk, wv, wproj);
    ln_stats<<<128, 512>>>(x);
    ln_apply<<<(TOT/4 + 255) / 256, 256>>>(x, gamma, beta);
    gemm_uv_tc<<<dim3(8, 256, B_), 256, 4 * SBUF * 4>>>();
    attn_mma<<<512, 256, ATTN_SMEM_FLOATS * 4>>>(x, out);
}

// round 6
// speedup vs baseline: 2.4380x; 1.0262x over previous
#include <cuda_runtime.h>
#include <math.h>
#include <stdint.h>

#define B_   4
#define C_   512
#define T_   32
#define HW_  1024
#define NCOL (T_*HW_)            // 32768 columns per batch
#define TOT  (B_*C_*T_*HW_)

// Scratch
__device__ float d_h[TOT];         // normalized input (tf32-rounded), [B,C,T,HW]
__device__ float d_u[TOT];         // u  = A   * h  (tf32-rounded)
__device__ float d_vp[TOT];        // v' = Wpv * h  (tf32-rounded)
__device__ float d_W2t[512*1024];  // combined weights [k][m], tf32-rounded
__device__ float d_mean[B_*T_];
__device__ float d_rstd[B_*T_];

__device__ __forceinline__ float tf32r(float x) {
    uint32_t r;
    asm("cvt.rna.tf32.f32 %0, %1;" : "=r"(r) : "f"(x));
    return __uint_as_float(r);
}

__device__ __forceinline__ void cp16(float* dst, const float* src) {
    unsigned d = (unsigned)__cvta_generic_to_shared(dst);
    asm volatile("cp.async.cg.shared.global [%0], [%1], 16;\n" :: "r"(d), "l"(src));
}

#define MMA_TF32(d0,d1,d2,d3,a0,a1,a2,a3,b0,b1) \
    asm volatile("mma.sync.aligned.m16n8k8.row.col.f32.tf32.tf32.f32 " \
                 "{%0,%1,%2,%3},{%4,%5,%6,%7},{%8,%9},{%0,%1,%2,%3};" \
                 : "+f"(d0), "+f"(d1), "+f"(d2), "+f"(d3) \
                 : "r"(a0), "r"(a1), "r"(a2), "r"(a3), "r"(b0), "r"(b1))

// ---------------------------------------------------------------------------
// prep_w2: W2t[k][m] tf32.  m<512: A[m][k]; m>=512: Wpv[m-512][k]
// ---------------------------------------------------------------------------
__global__ void prep_w2(const float* __restrict__ wq, const float* __restrict__ wk,
                        const float* __restrict__ wv, const float* __restrict__ wproj)
{
    int j = (blockIdx.x & 1) * 256 + threadIdx.x;   // k index
    int m = blockIdx.x >> 1;
    float acc = 0.f;
    if (m < 512) {
        #pragma unroll 4
        for (int o = 0; o < 512; o++)
            acc += wq[o*512 + m] * wk[o*512 + j];
    } else {
        int i = m - 512;
        #pragma unroll 4
        for (int c = 0; c < 512; c++)
            acc += wproj[i*512 + c] * wv[c*512 + j];
    }
    d_W2t[(size_t)j * 1024 + m] = tf32r(acc);
}

// ---------------------------------------------------------------------------
// LayerNorm stats (1024 threads/block for DRAM concurrency)
// ---------------------------------------------------------------------------
__global__ void ln_stats(const float* __restrict__ x)
{
    int g = blockIdx.x;
    int b = g >> 5, t = g & 31;
    const float4* base = reinterpret_cast<const float4*>(
        x + ((size_t)(b * C_) * T_ + t) * HW_);
    float s = 0.f, ss = 0.f;
    for (int i = threadIdx.x; i < 512*256; i += blockDim.x) {
        int c = i >> 8, hw4 = i & 255;
        float4 v = base[(size_t)c * (T_*HW_/4) + hw4];
        s  += v.x + v.y + v.z + v.w;
        ss += v.x*v.x + v.y*v.y + v.z*v.z + v.w*v.w;
    }
    __shared__ float sm[64];
    #pragma unroll
    for (int o = 16; o > 0; o >>= 1) {
        s  += __shfl_down_sync(0xffffffffu, s,  o);
        ss += __shfl_down_sync(0xffffffffu, ss, o);
    }
    int w = threadIdx.x >> 5;
    if ((threadIdx.x & 31) == 0) { sm[w] = s; sm[32 + w] = ss; }
    __syncthreads();
    if (threadIdx.x == 0) {
        float S = 0.f, SS = 0.f;
        int nw = blockDim.x >> 5;
        for (int k = 0; k < nw; k++) { S += sm[k]; SS += sm[32 + k]; }
        float invn = 1.f / (float)(C_ * HW_);
        float m   = S * invn;
        float var = SS * invn - m * m;
        d_mean[g] = m;
        d_rstd[g] = rsqrtf(var + 1e-6f);
    }
}

// ---------------------------------------------------------------------------
// LayerNorm apply -> tf32-rounded h
// ---------------------------------------------------------------------------
__global__ void ln_apply(const float* __restrict__ x,
                         const float* __restrict__ gamma,
                         const float* __restrict__ beta)
{
    size_t i4 = (size_t)blockIdx.x * blockDim.x + threadIdx.x;
    if (i4 >= (size_t)TOT/4) return;
    size_t i = i4 * 4;
    int t = (int)((i >> 10) & 31);
    int c = (int)((i >> 15) & 511);
    int b = (int)(i >> 24);
    int g = (b << 5) | t;
    float r  = d_rstd[g];
    float ga = gamma[c] * r;
    float be = beta[c] - d_mean[g] * ga;
    float4 v = reinterpret_cast<const float4*>(x)[i4];
    float4 o;
    o.x = tf32r(v.x*ga + be); o.y = tf32r(v.y*ga + be);
    o.z = tf32r(v.z*ga + be); o.w = tf32r(v.w*ga + be);
    reinterpret_cast<float4*>(d_h)[i4] = o;
}

// ---------------------------------------------------------------------------
// GEMM: [u;vp] = W2(1024x512) * h(512x32768) per batch. mma.sync tf32.
// Block 128x128, 4 warps (2x2), warp tile 64x64. 4-stage cp.async, k=16/stage.
// ---------------------------------------------------------------------------
#define SROW 136                 // 128 + 8 pad words
#define STW  (16*SROW)           // 2176 words per A or B stage tile
#define SBUF (2*STW)             // 4352 words per stage

__global__ __launch_bounds__(128, 2) void gemm_uv_tc()
{
    extern __shared__ float smem[];  // 4 stages * 4352 words = 69632 B
    int b  = blockIdx.z;
    int m0 = blockIdx.x * 128;       // m fastest -> B tile L2 reuse
    int n0 = blockIdx.y * 128;
    const float* hb = d_h + (size_t)b * C_ * NCOL;
    int tid  = threadIdx.x;
    int lane = tid & 31;
    int w    = tid >> 5;
    int warpM = w >> 1, warpN = w & 1;
    int g = lane >> 2, tq = lane & 3;
    int am = warpM * 64 + g;
    int bn = warpN * 64 + g;

    float acc[4][8][4];
    #pragma unroll
    for (int i = 0; i < 4; i++)
        #pragma unroll
        for (int j = 0; j < 8; j++)
            #pragma unroll
            for (int r = 0; r < 4; r++) acc[i][j][r] = 0.f;

    auto load_stage = [&](int k0, int buf) {
        float* As = smem + buf * SBUF;
        float* Bs = As + STW;
        #pragma unroll
        for (int r = 0; r < 4; r++) {
            int ch = r * 128 + tid;          // 0..511
            int k  = ch >> 5;
            int c4 = (ch & 31) * 4;
            cp16(&As[k * SROW + c4], &d_W2t[(size_t)(k0 + k) * 1024 + m0 + c4]);
            cp16(&Bs[k * SROW + c4], &hb[(size_t)(k0 + k) * NCOL + n0 + c4]);
        }
    };

    #pragma unroll
    for (int p = 0; p < 3; p++) {
        load_stage(p * 16, p);
        asm volatile("cp.async.commit_group;\n");
    }

    for (int it = 0; it < 32; it++) {
        asm volatile("cp.async.wait_group 2;\n");
        __syncthreads();

        const uint32_t* As = reinterpret_cast<const uint32_t*>(smem + (it & 3) * SBUF);
        const uint32_t* Bs = As + STW;

        #pragma unroll
        for (int kk = 0; kk < 16; kk += 8) {
            uint32_t a[4][4], bq[8][2];
            #pragma unroll
            for (int mf = 0; mf < 4; mf++) {
                int row = am + mf * 16;
                a[mf][0] = As[(kk + tq)     * SROW + row];
                a[mf][1] = As[(kk + tq)     * SROW + row + 8];
                a[mf][2] = As[(kk + tq + 4) * SROW + row];
                a[mf][3] = As[(kk + tq + 4) * SROW + row + 8];
            }
            #pragma unroll
            for (int nf = 0; nf < 8; nf++) {
                int col = bn + nf * 8;
                bq[nf][0] = Bs[(kk + tq)     * SROW + col];
                bq[nf][1] = Bs[(kk + tq + 4) * SROW + col];
            }
            #pragma unroll
            for (int mf = 0; mf < 4; mf++)
                #pragma unroll
                for (int nf = 0; nf < 8; nf++)
                    MMA_TF32(acc[mf][nf][0], acc[mf][nf][1], acc[mf][nf][2], acc[mf][nf][3],
                             a[mf][0], a[mf][1], a[mf][2], a[mf][3],
                             bq[nf][0], bq[nf][1]);
        }
        if (it + 3 < 32)
            load_stage((it + 3) * 16, (it + 3) & 3);
        asm volatile("cp.async.commit_group;\n");
    }

    // epilogue (tf32-rounded: consumed by tensor-core attention)
    bool isU = (m0 < 512);
    float* outbase = isU ? (d_u  + (size_t)(b * 512 + m0)       * NCOL)
                         : (d_vp + (size_t)(b * 512 + m0 - 512) * NCOL);
    #pragma unroll
    for (int mf = 0; mf < 4; mf++) {
        int mrow = warpM * 64 + mf * 16 + g;
        #pragma unroll
        for (int nf = 0; nf < 8; nf++) {
            int ncol = n0 + warpN * 64 + nf * 8 + tq * 2;
            float2 lo = make_float2(tf32r(acc[mf][nf][0]), tf32r(acc[mf][nf][1]));
            float2 hi = make_float2(tf32r(acc[mf][nf][2]), tf32r(acc[mf][nf][3]));
            *reinterpret_cast<float2*>(outbase + (size_t)mrow * NCOL + ncol)       = lo;
            *reinterpret_cast<float2*>(outbase + (size_t)(mrow + 8) * NCOL + ncol) = hi;
        }
    }
}

// ---------------------------------------------------------------------------
// Tensor-core attention + residual. Block = 8 pixels, 8 warps (warp = pixel).
// Register-prefetch double buffering hides global latency behind MMAs.
// SMEM layouts (pixel-last, bank-engineered odd strides) unchanged from R5.
// ---------------------------------------------------------------------------
#define HS_CSTR 296
#define GS_TSTR 292
#define VP_SSTR 168
#define OS_TSTR 164
#define ATTN_SMEM_FLOATS (9344 + 5376 + 5248)   // Gs + VPs + Os = 19968

__global__ __launch_bounds__(256, 2) void attn_mma(const float* __restrict__ x,
                                                   float* __restrict__ out)
{
    extern __shared__ float sm[];
    float* Hs  = sm;                 // 16*296 = 4736 (phase1)
    float* Us  = sm + 4736;          // 4736          (phase1)
    float* Gs  = sm;                 // 32*292 = 9344 (aliases Hs/Us)
    float* VPs = sm + 9344;          // 32*168 = 5376
    float* Os  = sm + 14720;         // 32*164 = 5248

    int blk = blockIdx.x;            // 0..511
    int b   = blk >> 7;
    int hw0 = (blk & 127) * 8;
    int tid  = threadIdx.x;
    int lane = tid & 31;
    int px   = tid >> 5;             // warp = pixel 0..7
    int g = lane >> 2, tq = lane & 3;
    const size_t pixbase = (size_t)b * C_ * T_ * HW_ + hw0;
    const float* hg = d_h  + pixbase;
    const float* ug = d_u  + pixbase;
    const float* vg = d_vp + pixbase;

    // ---------------- phase 1: logits ----------------
    float acc1[2][4][4];
    #pragma unroll
    for (int i = 0; i < 2; i++)
        #pragma unroll
        for (int j = 0; j < 4; j++)
            #pragma unroll
            for (int r = 0; r < 4; r++) acc1[i][j][r] = 0.f;

    float4 ph[4], pu[4];
    auto prefetch1 = [&](int c0) {
        #pragma unroll
        for (int r = 0; r < 4; r++) {
            int flat = r * 256 + tid;            // float4 units, 0..1023
            int pp = flat & 1;
            int t  = (flat >> 1) & 31;
            int c  = flat >> 6;                  // 0..15
            size_t go = ((size_t)(c0 + c) * 32 + t) * 1024 + pp * 4;
            ph[r] = *reinterpret_cast<const float4*>(hg + go);
            pu[r] = *reinterpret_cast<const float4*>(ug + go);
        }
    };
    auto store1 = [&]() {
        #pragma unroll
        for (int r = 0; r < 4; r++) {
            int flat = r * 256 + tid;
            int pp = flat & 1;
            int t  = (flat >> 1) & 31;
            int c  = flat >> 6;
            int so = c * HS_CSTR + t * 9 + pp * 4;
            Hs[so] = ph[r].x; Hs[so+1] = ph[r].y; Hs[so+2] = ph[r].z; Hs[so+3] = ph[r].w;
            Us[so] = pu[r].x; Us[so+1] = pu[r].y; Us[so+2] = pu[r].z; Us[so+3] = pu[r].w;
        }
    };

    prefetch1(0);
    for (int c0 = 0; c0 < 512; c0 += 16) {
        store1();
        __syncthreads();
        if (c0 + 16 < 512) prefetch1(c0 + 16);

        const uint32_t* Hu = reinterpret_cast<const uint32_t*>(Hs);
        const uint32_t* Uu = reinterpret_cast<const uint32_t*>(Us);
        #pragma unroll
        for (int kk = 0; kk < 16; kk += 8) {
            uint32_t a[2][4], bq[4][2];
            #pragma unroll
            for (int mf = 0; mf < 2; mf++) {
                int base = (kk + tq) * HS_CSTR + (mf * 16 + g) * 9 + px;
                a[mf][0] = Hu[base];
                a[mf][1] = Hu[base + 72];                        // t+8
                a[mf][2] = Hu[base + 4 * HS_CSTR];               // k+4
                a[mf][3] = Hu[base + 4 * HS_CSTR + 72];
            }
            #pragma unroll
            for (int nf = 0; nf < 4; nf++) {
                int base = (kk + tq) * HS_CSTR + (nf * 8 + g) * 9 + px;
                bq[nf][0] = Uu[base];
                bq[nf][1] = Uu[base + 4 * HS_CSTR];
            }
            #pragma unroll
            for (int mf = 0; mf < 2; mf++)
                #pragma unroll
                for (int nf = 0; nf < 4; nf++)
                    MMA_TF32(acc1[mf][nf][0], acc1[mf][nf][1], acc1[mf][nf][2], acc1[mf][nf][3],
                             a[mf][0], a[mf][1], a[mf][2], a[mf][3],
                             bq[nf][0], bq[nf][1]);
        }
        __syncthreads();
    }

    // write scaled logits into Gs
    const float scale = 0.044194173824159216f;   // 512^-0.5
    #pragma unroll
    for (int mf = 0; mf < 2; mf++) {
        #pragma unroll
        for (int nf = 0; nf < 4; nf++) {
            int t = mf * 16 + g;
            int s = nf * 8 + tq * 2;
            Gs[t * GS_TSTR + s * 9 + px]             = acc1[mf][nf][0] * scale;
            Gs[t * GS_TSTR + (s + 1) * 9 + px]       = acc1[mf][nf][1] * scale;
            Gs[(t + 8) * GS_TSTR + s * 9 + px]       = acc1[mf][nf][2] * scale;
            Gs[(t + 8) * GS_TSTR + (s + 1) * 9 + px] = acc1[mf][nf][3] * scale;
        }
    }
    __syncthreads();

    // ---------------- causal softmax (thread = (px_s, t) row) ----------------
    {
        int px_s = tid & 7;
        int t    = tid >> 3;
        int base = t * GS_TSTR + px_s;
        float mx = -1e30f;
        for (int s = 0; s <= t; s++) mx = fmaxf(mx, Gs[base + s * 9]);
        float Z = 0.f;
        for (int s = 0; s <= t; s++) Z += __expf(Gs[base + s * 9] - mx);
        float iz = 1.f / Z;
        for (int s = 0; s < 32; s++) {
            float v = (s <= t) ? __expf(Gs[base + s * 9] - mx) * iz : 0.f;
            Gs[base + s * 9] = tf32r(v);
        }
    }
    __syncthreads();

    // ---------------- phase 4: out = G @ vp^T + x ----------------
    const uint32_t* Gu = reinterpret_cast<const uint32_t*>(Gs);
    float4 pv[4];
    auto prefetch4 = [&](int oc) {
        #pragma unroll
        for (int r = 0; r < 4; r++) {
            int flat = r * 256 + tid;            // 0..1023 float4 units
            int pp = flat & 1;
            int s  = (flat >> 1) & 31;
            int o  = flat >> 6;                  // 0..15
            size_t go = ((size_t)(oc + o) * 32 + s) * 1024 + pp * 4;
            pv[r] = *reinterpret_cast<const float4*>(vg + go);
        }
    };

    prefetch4(0);
    for (int oc = 0; oc < 512; oc += 16) {
        #pragma unroll
        for (int r = 0; r < 4; r++) {
            int flat = r * 256 + tid;
            int pp = flat & 1;
            int s  = (flat >> 1) & 31;
            int o  = flat >> 6;
            int so = s * VP_SSTR + o * 9 + pp * 4;
            VPs[so] = pv[r].x; VPs[so+1] = pv[r].y; VPs[so+2] = pv[r].z; VPs[so+3] = pv[r].w;
        }
        __syncthreads();
        if (oc + 16 < 512) prefetch4(oc + 16);

        float acc2[2][2][4];
        #pragma unroll
        for (int i = 0; i < 2; i++)
            #pragma unroll
            for (int j = 0; j < 2; j++)
                #pragma unroll
                for (int r = 0; r < 4; r++) acc2[i][j][r] = 0.f;

        const uint32_t* Vu = reinterpret_cast<const uint32_t*>(VPs);
        #pragma unroll
        for (int kk = 0; kk < 32; kk += 8) {
            uint32_t a[2][4], bq[2][2];
            #pragma unroll
            for (int mf = 0; mf < 2; mf++) {
                int base = (mf * 16 + g) * GS_TSTR + (kk + tq) * 9 + px;
                a[mf][0] = Gu[base];
                a[mf][1] = Gu[base + 8 * GS_TSTR];   // t+8
                a[mf][2] = Gu[base + 36];            // k+4
                a[mf][3] = Gu[base + 8 * GS_TSTR + 36];
            }
            #pragma unroll
            for (int nf = 0; nf < 2; nf++) {
                int base = (kk + tq) * VP_SSTR + (nf * 8 + g) * 9 + px;
                bq[nf][0] = Vu[base];
                bq[nf][1] = Vu[base + 4 * VP_SSTR];
            }
            #pragma unroll
            for (int mf = 0; mf < 2; mf++)
                #pragma unroll
                for (int nf = 0; nf < 2; nf++)
                    MMA_TF32(acc2[mf][nf][0], acc2[mf][nf][1], acc2[mf][nf][2], acc2[mf][nf][3],
                             a[mf][0], a[mf][1], a[mf][2], a[mf][3],
                             bq[nf][0], bq[nf][1]);
        }

        // frags -> Os
        #pragma unroll
        for (int mf = 0; mf < 2; mf++) {
            #pragma unroll
            for (int nf = 0; nf < 2; nf++) {
                int t = mf * 16 + g;
                int o = nf * 8 + tq * 2;
                Os[t * OS_TSTR + o * 10 + px]             = acc2[mf][nf][0];
                Os[t * OS_TSTR + (o + 1) * 10 + px]       = acc2[mf][nf][1];
                Os[(t + 8) * OS_TSTR + o * 10 + px]       = acc2[mf][nf][2];
                Os[(t + 8) * OS_TSTR + (o + 1) * 10 + px] = acc2[mf][nf][3];
            }
        }
        __syncthreads();

        // Os + x -> out (coalesced float4)
        #pragma unroll
        for (int r = 0; r < 4; r++) {
            int flat = r * 256 + tid;
            int pp = flat & 1;
            int t  = (flat >> 1) & 31;
            int o  = flat >> 6;
            size_t gg = pixbase + ((size_t)(oc + o) * 32 + t) * 1024 + pp * 4;
            float4 xv = *reinterpret_cast<const float4*>(x + gg);
            int so = t * OS_TSTR + o * 10 + pp * 4;
            float4 ov;
            ov.x = Os[so]     + xv.x;
            ov.y = Os[so + 1] + xv.y;
            ov.z = Os[so + 2] + xv.z;
            ov.w = Os[so + 3] + xv.w;
            *reinterpret_cast<float4*>(out + gg) = ov;
        }
        __syncthreads();
    }
}

// ---------------------------------------------------------------------------
extern "C" void kernel_launch(void* const* d_in, const int* in_sizes, int n_in,
                              void* d_out, int out_size)
{
    const float* x     = (const float*)d_in[0];
    const float* gamma = (const float*)d_in[1];
    const float* beta  = (const float*)d_in[2];
    const float* wq    = (const float*)d_in[3];
    const float* wk    = (const float*)d_in[4];
    const float* wv    = (const float*)d_in[5];
    const float* wproj = (const float*)d_in[6];
    float* out = (float*)d_out;

    cudaFuncSetAttribute(gemm_uv_tc, cudaFuncAttributeMaxDynamicSharedMemorySize,
                         4 * SBUF * 4);
    cudaFuncSetAttribute(attn_mma, cudaFuncAttributeMaxDynamicSharedMemorySize,
                         ATTN_SMEM_FLOATS * 4);

    prep_w2<<<2048, 256>>>(wq, wk, wv, wproj);
    ln_stats<<<128, 1024>>>(x);
    ln_apply<<<(TOT/4 + 255) / 256, 256>>>(x, gamma, beta);
    gemm_uv_tc<<<dim3(8, 256, B_), 128, 4 * SBUF * 4>>>();
    attn_mma<<<512, 256, ATTN_SMEM_FLOATS * 4>>>(x, out);
}

// round 7
// speedup vs baseline: 2.5193x; 1.0334x over previous
#include <cuda_runtime.h>
#include <math.h>
#include <stdint.h>

#define B_   4
#define C_   512
#define T_   32
#define HW_  1024
#define NCOL (T_*HW_)            // 32768 columns per batch
#define TOT  (B_*C_*T_*HW_)

// Scratch
__device__ float d_u[TOT];         // u  = A·h   reconstructed from x-GEMM + LN algebra
__device__ float d_vp[TOT];        // v' = Wpv·h
__device__ float d_W2t[512*1024];  // W2G = W2·diag(gamma), transposed [k][m], tf32
__device__ float d_w2g1[1024];     // row sums of W2G   ((W2G)·1)
__device__ float d_w2b[1024];      // W2·beta
__device__ float d_mean[B_*T_];
__device__ float d_rstd[B_*T_];

__device__ __forceinline__ float tf32r(float x) {
    uint32_t r;
    asm("cvt.rna.tf32.f32 %0, %1;" : "=r"(r) : "f"(x));
    return __uint_as_float(r);
}

__device__ __forceinline__ void cp16(float* dst, const float* src) {
    unsigned d = (unsigned)__cvta_generic_to_shared(dst);
    asm volatile("cp.async.cg.shared.global [%0], [%1], 16;\n" :: "r"(d), "l"(src));
}

#define MMA_TF32(d0,d1,d2,d3,a0,a1,a2,a3,b0,b1) \
    asm volatile("mma.sync.aligned.m16n8k8.row.col.f32.tf32.tf32.f32 " \
                 "{%0,%1,%2,%3},{%4,%5,%6,%7},{%8,%9},{%0,%1,%2,%3};" \
                 : "+f"(d0), "+f"(d1), "+f"(d2), "+f"(d3) \
                 : "r"(a0), "r"(a1), "r"(a2), "r"(a3), "r"(b0), "r"(b1))

// ---------------------------------------------------------------------------
// prep_w2: one block per output row m (0..1023).
//   raw[m][j]: m<512: A[m][j]=sum_o wq[o,m]wk[o,j]; m>=512: Wpv[m-512][j]
//   d_W2t[j][m] = tf32r(raw*gamma[j]);  d_w2g1[m] = sum_j d_W2t;  d_w2b[m]=raw.beta
// ---------------------------------------------------------------------------
__global__ void prep_w2(const float* __restrict__ wq, const float* __restrict__ wk,
                        const float* __restrict__ wv, const float* __restrict__ wproj,
                        const float* __restrict__ gamma, const float* __restrict__ beta)
{
    int m = blockIdx.x;
    int tid = threadIdx.x;
    float lg = 0.f, lb = 0.f;
    #pragma unroll
    for (int jj = 0; jj < 2; jj++) {
        int j = jj * 256 + tid;
        float acc = 0.f;
        if (m < 512) {
            #pragma unroll 4
            for (int o = 0; o < 512; o++)
                acc += wq[o*512 + m] * wk[o*512 + j];
        } else {
            int i = m - 512;
            #pragma unroll 4
            for (int c = 0; c < 512; c++)
                acc += wproj[i*512 + c] * wv[c*512 + j];
        }
        float wg = tf32r(acc * gamma[j]);
        d_W2t[(size_t)j * 1024 + m] = wg;
        lg += wg;
        lb += acc * beta[j];
    }
    __shared__ float red[16];
    #pragma unroll
    for (int o = 16; o > 0; o >>= 1) {
        lg += __shfl_down_sync(0xffffffffu, lg, o);
        lb += __shfl_down_sync(0xffffffffu, lb, o);
    }
    int w = tid >> 5;
    if ((tid & 31) == 0) { red[w] = lg; red[8 + w] = lb; }
    __syncthreads();
    if (tid == 0) {
        float G = 0.f, Bv = 0.f;
        for (int k = 0; k < 8; k++) { G += red[k]; Bv += red[8 + k]; }
        d_w2g1[m] = G;
        d_w2b[m]  = Bv;
    }
}

// ---------------------------------------------------------------------------
// LayerNorm stats
// ---------------------------------------------------------------------------
__global__ void ln_stats(const float* __restrict__ x)
{
    int g = blockIdx.x;
    int b = g >> 5, t = g & 31;
    const float4* base = reinterpret_cast<const float4*>(
        x + ((size_t)(b * C_) * T_ + t) * HW_);
    float s = 0.f, ss = 0.f;
    for (int i = threadIdx.x; i < 512*256; i += blockDim.x) {
        int c = i >> 8, hw4 = i & 255;
        float4 v = base[(size_t)c * (T_*HW_/4) + hw4];
        s  += v.x + v.y + v.z + v.w;
        ss += v.x*v.x + v.y*v.y + v.z*v.z + v.w*v.w;
    }
    __shared__ float sm[64];
    #pragma unroll
    for (int o = 16; o > 0; o >>= 1) {
        s  += __shfl_down_sync(0xffffffffu, s,  o);
        ss += __shfl_down_sync(0xffffffffu, ss, o);
    }
    int w = threadIdx.x >> 5;
    if ((threadIdx.x & 31) == 0) { sm[w] = s; sm[32 + w] = ss; }
    __syncthreads();
    if (threadIdx.x == 0) {
        float S = 0.f, SS = 0.f;
        int nw = blockDim.x >> 5;
        for (int k = 0; k < nw; k++) { S += sm[k]; SS += sm[32 + k]; }
        float invn = 1.f / (float)(C_ * HW_);
        float m   = S * invn;
        float var = SS * invn - m * m;
        d_mean[g] = m;
        d_rstd[g] = rsqrtf(var + 1e-6f);
    }
}

// ---------------------------------------------------------------------------
// GEMM on raw x: y = W2G·x; epilogue u/vp = rstd_g·y + (w2b - rstd_g·mean_g·w2g1)
// Block 128x128, 4 warps (2x2), warp tile 64x64. 4-stage cp.async, k=16/stage.
// Each 128-wide n-tile has a single t (n = t*1024+hw) -> scalar g per block.
// ---------------------------------------------------------------------------
#define SROW 136                 // 128 + 8 pad words
#define STW  (16*SROW)           // 2176 words per A or B stage tile
#define SBUF (2*STW)             // 4352 words per stage

__global__ __launch_bounds__(128, 2) void gemm_uv_tc(const float* __restrict__ x)
{
    extern __shared__ float smem[];  // 4 stages * 4352 words = 69632 B
    int b  = blockIdx.z;
    int m0 = blockIdx.x * 128;       // m fastest -> B tile L2 reuse
    int n0 = blockIdx.y * 128;
    const float* xb = x + (size_t)b * C_ * NCOL;
    int tid  = threadIdx.x;
    int lane = tid & 31;
    int w    = tid >> 5;
    int warpM = w >> 1, warpN = w & 1;
    int g = lane >> 2, tq = lane & 3;
    int am = warpM * 64 + g;
    int bn = warpN * 64 + g;

    float acc[4][8][4];
    #pragma unroll
    for (int i = 0; i < 4; i++)
        #pragma unroll
        for (int j = 0; j < 8; j++)
            #pragma unroll
            for (int r = 0; r < 4; r++) acc[i][j][r] = 0.f;

    auto load_stage = [&](int k0, int buf) {
        float* As = smem + buf * SBUF;
        float* Bs = As + STW;
        #pragma unroll
        for (int r = 0; r < 4; r++) {
            int ch = r * 128 + tid;          // 0..511
            int k  = ch >> 5;
            int c4 = (ch & 31) * 4;
            cp16(&As[k * SROW + c4], &d_W2t[(size_t)(k0 + k) * 1024 + m0 + c4]);
            cp16(&Bs[k * SROW + c4], &xb[(size_t)(k0 + k) * NCOL + n0 + c4]);
        }
    };

    #pragma unroll
    for (int p = 0; p < 3; p++) {
        load_stage(p * 16, p);
        asm volatile("cp.async.commit_group;\n");
    }

    for (int it = 0; it < 32; it++) {
        asm volatile("cp.async.wait_group 2;\n");
        __syncthreads();

        const uint32_t* As = reinterpret_cast<const uint32_t*>(smem + (it & 3) * SBUF);
        const uint32_t* Bs = As + STW;

        #pragma unroll
        for (int kk = 0; kk < 16; kk += 8) {
            uint32_t a[4][4], bq[8][2];
            #pragma unroll
            for (int mf = 0; mf < 4; mf++) {
                int row = am + mf * 16;
                a[mf][0] = As[(kk + tq)     * SROW + row];
                a[mf][1] = As[(kk + tq)     * SROW + row + 8];
                a[mf][2] = As[(kk + tq + 4) * SROW + row];
                a[mf][3] = As[(kk + tq + 4) * SROW + row + 8];
            }
            #pragma unroll
            for (int nf = 0; nf < 8; nf++) {
                int col = bn + nf * 8;
                bq[nf][0] = Bs[(kk + tq)     * SROW + col];
                bq[nf][1] = Bs[(kk + tq + 4) * SROW + col];
            }
            #pragma unroll
            for (int mf = 0; mf < 4; mf++)
                #pragma unroll
                for (int nf = 0; nf < 8; nf++)
                    MMA_TF32(acc[mf][nf][0], acc[mf][nf][1], acc[mf][nf][2], acc[mf][nf][3],
                             a[mf][0], a[mf][1], a[mf][2], a[mf][3],
                             bq[nf][0], bq[nf][1]);
        }
        if (it + 3 < 32)
            load_stage((it + 3) * 16, (it + 3) & 3);
        asm volatile("cp.async.commit_group;\n");
    }

    // epilogue: LN correction + tf32 rounding
    int tcol = blockIdx.y >> 3;              // t of this n-tile
    int gidx = b * 32 + tcol;
    float rstdv = d_rstd[gidx];
    float rm    = rstdv * d_mean[gidx];
    bool isU = (m0 < 512);
    float* outbase = isU ? (d_u  + (size_t)(b * 512 + m0)       * NCOL)
                         : (d_vp + (size_t)(b * 512 + m0 - 512) * NCOL);
    #pragma unroll
    for (int mf = 0; mf < 4; mf++) {
        int mrow = warpM * 64 + mf * 16 + g;
        int mg0 = m0 + mrow, mg1 = m0 + mrow + 8;
        float bias0 = d_w2b[mg0] - rm * d_w2g1[mg0];
        float bias1 = d_w2b[mg1] - rm * d_w2g1[mg1];
        #pragma unroll
        for (int nf = 0; nf < 8; nf++) {
            int ncol = n0 + warpN * 64 + nf * 8 + tq * 2;
            float2 lo = make_float2(tf32r(rstdv * acc[mf][nf][0] + bias0),
                                    tf32r(rstdv * acc[mf][nf][1] + bias0));
            float2 hi = make_float2(tf32r(rstdv * acc[mf][nf][2] + bias1),
                                    tf32r(rstdv * acc[mf][nf][3] + bias1));
            *reinterpret_cast<float2*>(outbase + (size_t)mrow * NCOL + ncol)       = lo;
            *reinterpret_cast<float2*>(outbase + (size_t)(mrow + 8) * NCOL + ncol) = hi;
        }
    }
}

// ---------------------------------------------------------------------------
// Tensor-core attention + residual, LN folded.
// Phase1 raw[t][s] = (gamma.x_t)^T u_s via mma; gu_s=gamma^T u_s, bu_s=beta^T u_s
// accumulated SIMT from the same smem chunks. logits = (rstd_t*(raw - mean_t*gu_s)
// + bu_s)*scale. Softmax, then phase4 out = G@vp^T + x.
// ---------------------------------------------------------------------------
#define HS_CSTR 296
#define GS_TSTR 292
#define VP_SSTR 168
#define OS_TSTR 164
#define ATTN_SMEM_FLOATS (9344 + 5376 + 5248)   // 19968 floats

__global__ __launch_bounds__(256, 2) void attn_mma(const float* __restrict__ x,
                                                   const float* __restrict__ gamma,
                                                   const float* __restrict__ beta,
                                                   float* __restrict__ out)
{
    extern __shared__ float sm[];
    float* Hs  = sm;                 // 16*296 = 4736 (phase1)
    float* Us  = sm + 4736;          // 4736          (phase1)
    float* Gs  = sm;                 // 32*292 = 9344 (aliases Hs/Us after phase1)
    float* VPs = sm + 9344;          // 32*168 = 5376
    float* Os  = sm + 14720;         // 32*164 = 5248
    float* gus = sm + 14720;         // 256 (phase1 tail; Os region, disjoint in time)
    float* bus = sm + 14976;         // 256
    float* smG = sm + 15800;         // 16 gamma chunk
    float* smB = sm + 15816;         // 16 beta chunk

    int blk = blockIdx.x;            // 0..511
    int b   = blk >> 7;
    int hw0 = (blk & 127) * 8;
    int tid  = threadIdx.x;
    int lane = tid & 31;
    int px   = tid >> 5;             // warp = pixel 0..7
    int g = lane >> 2, tq = lane & 3;
    const size_t pixbase = (size_t)b * C_ * T_ * HW_ + hw0;
    const float* xg = x    + pixbase;
    const float* ug = d_u  + pixbase;
    const float* vg = d_vp + pixbase;

    int s_ = tid >> 3, px_ = tid & 7;    // (s,pixel) ownership for gu/bu
    float gu = 0.f, bu = 0.f;

    // ---------------- phase 1: raw logits ----------------
    float acc1[2][4][4];
    #pragma unroll
    for (int i = 0; i < 2; i++)
        #pragma unroll
        for (int j = 0; j < 4; j++)
            #pragma unroll
            for (int r = 0; r < 4; r++) acc1[i][j][r] = 0.f;

    float4 ph[4], pu[4];
    auto prefetch1 = [&](int c0) {
        #pragma unroll
        for (int r = 0; r < 4; r++) {
            int flat = r * 256 + tid;            // float4 units, 0..1023
            int pp = flat & 1;
            int t  = (flat >> 1) & 31;
            int c  = flat >> 6;                  // 0..15
            size_t go = ((size_t)(c0 + c) * 32 + t) * 1024 + pp * 4;
            ph[r] = *reinterpret_cast<const float4*>(xg + go);
            pu[r] = *reinterpret_cast<const float4*>(ug + go);
        }
    };
    auto store1 = [&](int c0) {
        #pragma unroll
        for (int r = 0; r < 4; r++) {
            int flat = r * 256 + tid;
            int pp = flat & 1;
            int t  = (flat >> 1) & 31;
            int c  = flat >> 6;
            float gam = gamma[c0 + c];
            int so = c * HS_CSTR + t * 9 + pp * 4;
            Hs[so] = gam*ph[r].x; Hs[so+1] = gam*ph[r].y;
            Hs[so+2] = gam*ph[r].z; Hs[so+3] = gam*ph[r].w;
            Us[so] = pu[r].x; Us[so+1] = pu[r].y; Us[so+2] = pu[r].z; Us[so+3] = pu[r].w;
        }
    };

    prefetch1(0);
    for (int c0 = 0; c0 < 512; c0 += 16) {
        store1(c0);
        if (tid < 16)       smG[tid]      = gamma[c0 + tid];
        else if (tid < 32)  smB[tid - 16] = beta[c0 + tid - 16];
        __syncthreads();
        if (c0 + 16 < 512) prefetch1(c0 + 16);

        const uint32_t* Hu = reinterpret_cast<const uint32_t*>(Hs);
        const uint32_t* Uu = reinterpret_cast<const uint32_t*>(Us);
        #pragma unroll
        for (int kk = 0; kk < 16; kk += 8) {
            uint32_t a[2][4], bq[4][2];
            #pragma unroll
            for (int mf = 0; mf < 2; mf++) {
                int base = (kk + tq) * HS_CSTR + (mf * 16 + g) * 9 + px;
                a[mf][0] = Hu[base];
                a[mf][1] = Hu[base + 72];                        // t+8
                a[mf][2] = Hu[base + 4 * HS_CSTR];               // k+4
                a[mf][3] = Hu[base + 4 * HS_CSTR + 72];
            }
            #pragma unroll
            for (int nf = 0; nf < 4; nf++) {
                int base = (kk + tq) * HS_CSTR + (nf * 8 + g) * 9 + px;
                bq[nf][0] = Uu[base];
                bq[nf][1] = Uu[base + 4 * HS_CSTR];
            }
            #pragma unroll
            for (int mf = 0; mf < 2; mf++)
                #pragma unroll
                for (int nf = 0; nf < 4; nf++)
                    MMA_TF32(acc1[mf][nf][0], acc1[mf][nf][1], acc1[mf][nf][2], acc1[mf][nf][3],
                             a[mf][0], a[mf][1], a[mf][2], a[mf][3],
                             bq[nf][0], bq[nf][1]);
        }
        // gu/bu accumulation from the same u chunk
        #pragma unroll
        for (int c = 0; c < 16; c++) {
            float uv = Us[c * HS_CSTR + s_ * 9 + px_];
            gu += smG[c] * uv;
            bu += smB[c] * uv;
        }
        __syncthreads();
    }

    gus[s_ * 8 + px_] = gu;
    bus[s_ * 8 + px_] = bu;
    __syncthreads();

    // corrected, scaled logits -> Gs
    const float scale = 0.044194173824159216f;   // 512^-0.5
    #pragma unroll
    for (int mf = 0; mf < 2; mf++) {
        int t0 = mf * 16 + g, t1 = t0 + 8;
        float r0 = d_rstd[b*32 + t0], m0v = d_mean[b*32 + t0];
        float r1 = d_rstd[b*32 + t1], m1v = d_mean[b*32 + t1];
        #pragma unroll
        for (int nf = 0; nf < 4; nf++) {
            int s0 = nf * 8 + tq * 2, s1 = s0 + 1;
            float gu0 = gus[s0*8 + px], bu0 = bus[s0*8 + px];
            float gu1 = gus[s1*8 + px], bu1 = bus[s1*8 + px];
            Gs[t0 * GS_TSTR + s0 * 9 + px] = (r0*(acc1[mf][nf][0] - m0v*gu0) + bu0) * scale;
            Gs[t0 * GS_TSTR + s1 * 9 + px] = (r0*(acc1[mf][nf][1] - m0v*gu1) + bu1) * scale;
            Gs[t1 * GS_TSTR + s0 * 9 + px] = (r1*(acc1[mf][nf][2] - m1v*gu0) + bu0) * scale;
            Gs[t1 * GS_TSTR + s1 * 9 + px] = (r1*(acc1[mf][nf][3] - m1v*gu1) + bu1) * scale;
        }
    }
    __syncthreads();

    // ---------------- causal softmax ----------------
    {
        int base = s_ * 0;  (void)base;
        int pxs = tid & 7;
        int t   = tid >> 3;
        int gb  = t * GS_TSTR + pxs;
        float mx = -1e30f;
        for (int s = 0; s <= t; s++) mx = fmaxf(mx, Gs[gb + s * 9]);
        float Z = 0.f;
        for (int s = 0; s <= t; s++) Z += __expf(Gs[gb + s * 9] - mx);
        float iz = 1.f / Z;
        for (int s = 0; s < 32; s++) {
            float v = (s <= t) ? __expf(Gs[gb + s * 9] - mx) * iz : 0.f;
            Gs[gb + s * 9] = tf32r(v);
        }
    }
    __syncthreads();

    // ---------------- phase 4: out = G @ vp^T + x ----------------
    const uint32_t* Gu = reinterpret_cast<const uint32_t*>(Gs);
    float4 pv[4];
    auto prefetch4 = [&](int oc) {
        #pragma unroll
        for (int r = 0; r < 4; r++) {
            int flat = r * 256 + tid;            // float4 units
            int pp = flat & 1;
            int s  = (flat >> 1) & 31;
            int o  = flat >> 6;                  // 0..15
            size_t go = ((size_t)(oc + o) * 32 + s) * 1024 + pp * 4;
            pv[r] = *reinterpret_cast<const float4*>(vg + go);
        }
    };

    prefetch4(0);
    for (int oc = 0; oc < 512; oc += 16) {
        #pragma unroll
        for (int r = 0; r < 4; r++) {
            int flat = r * 256 + tid;
            int pp = flat & 1;
            int s  = (flat >> 1) & 31;
            int o  = flat >> 6;
            int so = s * VP_SSTR + o * 9 + pp * 4;
            VPs[so] = pv[r].x; VPs[so+1] = pv[r].y; VPs[so+2] = pv[r].z; VPs[so+3] = pv[r].w;
        }
        __syncthreads();
        if (oc + 16 < 512) prefetch4(oc + 16);

        float acc2[2][2][4];
        #pragma unroll
        for (int i = 0; i < 2; i++)
            #pragma unroll
            for (int j = 0; j < 2; j++)
                #pragma unroll
                for (int r = 0; r < 4; r++) acc2[i][j][r] = 0.f;

        const uint32_t* Vu = reinterpret_cast<const uint32_t*>(VPs);
        #pragma unroll
        for (int kk = 0; kk < 32; kk += 8) {
            uint32_t a[2][4], bq[2][2];
            #pragma unroll
            for (int mf = 0; mf < 2; mf++) {
                int base = (mf * 16 + g) * GS_TSTR + (kk + tq) * 9 + px;
                a[mf][0] = Gu[base];
                a[mf][1] = Gu[base + 8 * GS_TSTR];   // t+8
                a[mf][2] = Gu[base + 36];            // k+4
                a[mf][3] = Gu[base + 8 * GS_TSTR + 36];
            }
            #pragma unroll
            for (int nf = 0; nf < 2; nf++) {
                int base = (kk + tq) * VP_SSTR + (nf * 8 + g) * 9 + px;
                bq[nf][0] = Vu[base];
                bq[nf][1] = Vu[base + 4 * VP_SSTR];
            }
            #pragma unroll
            for (int mf = 0; mf < 2; mf++)
                #pragma unroll
                for (int nf = 0; nf < 2; nf++)
                    MMA_TF32(acc2[mf][nf][0], acc2[mf][nf][1], acc2[mf][nf][2], acc2[mf][nf][3],
                             a[mf][0], a[mf][1], a[mf][2], a[mf][3],
                             bq[nf][0], bq[nf][1]);
        }

        #pragma unroll
        for (int mf = 0; mf < 2; mf++) {
            #pragma unroll
            for (int nf = 0; nf < 2; nf++) {
                int t = mf * 16 + g;
                int o = nf * 8 + tq * 2;
                Os[t * OS_TSTR + o * 10 + px]             = acc2[mf][nf][0];
                Os[t * OS_TSTR + (o + 1) * 10 + px]       = acc2[mf][nf][1];
                Os[(t + 8) * OS_TSTR + o * 10 + px]       = acc2[mf][nf][2];
                Os[(t + 8) * OS_TSTR + (o + 1) * 10 + px] = acc2[mf][nf][3];
            }
        }
        __syncthreads();

        #pragma unroll
        for (int r = 0; r < 4; r++) {
            int flat = r * 256 + tid;
            int pp = flat & 1;
            int t  = (flat >> 1) & 31;
            int o  = flat >> 6;
            size_t gg = pixbase + ((size_t)(oc + o) * 32 + t) * 1024 + pp * 4;
            float4 xv = *reinterpret_cast<const float4*>(x + gg);
            int so = t * OS_TSTR + o * 10 + pp * 4;
            float4 ov;
            ov.x = Os[so]     + xv.x;
            ov.y = Os[so + 1] + xv.y;
            ov.z = Os[so + 2] + xv.z;
            ov.w = Os[so + 3] + xv.w;
            *reinterpret_cast<float4*>(out + gg) = ov;
        }
        __syncthreads();
    }
}

// ---------------------------------------------------------------------------
extern "C" void kernel_launch(void* const* d_in, const int* in_sizes, int n_in,
                              void* d_out, int out_size)
{
    const float* x     = (const float*)d_in[0];
    const float* gamma = (const float*)d_in[1];
    const float* beta  = (const float*)d_in[2];
    const float* wq    = (const float*)d_in[3];
    const float* wk    = (const float*)d_in[4];
    const float* wv    = (const float*)d_in[5];
    const float* wproj = (const float*)d_in[6];
    float* out = (float*)d_out;

    cudaFuncSetAttribute(gemm_uv_tc, cudaFuncAttributeMaxDynamicSharedMemorySize,
                         4 * SBUF * 4);
    cudaFuncSetAttribute(attn_mma, cudaFuncAttributeMaxDynamicSharedMemorySize,
                         ATTN_SMEM_FLOATS * 4);

    prep_w2<<<1024, 256>>>(wq, wk, wv, wproj, gamma, beta);
    ln_stats<<<128, 1024>>>(x);
    gemm_uv_tc<<<dim3(8, 256, B_), 128, 4 * SBUF * 4>>>(x);
    attn_mma<<<512, 256, ATTN_SMEM_FLOATS * 4>>>(x, gamma, beta, out);
}

// round 8
// speedup vs baseline: 2.9332x; 1.1643x over previous
#include <cuda_runtime.h>
#include <cuda_fp16.h>
#include <math.h>
#include <stdint.h>

#define B_   4
#define C_   512
#define T_   32
#define HW_  1024
#define NCOL (T_*HW_)            // 32768 columns per batch
#define TOT  (B_*C_*T_*HW_)

// Scratch
__device__ __half d_x16[TOT];      // x transposed+fp16: [b][n][c] (n = t*1024+hw)
__device__ __half d_W16[1024*512]; // W2G = W2·diag(gamma), [m][k], fp16
__device__ float  d_u[TOT];        // u  (fp32, [b][c][n])
__device__ float  d_vp[TOT];       // v' (fp32, [b][c][n])
__device__ float  d_w2g1[1024];    // row sums of W16
__device__ float  d_w2b[1024];     // W2·beta
__device__ float  d_mean[B_*T_];
__device__ float  d_rstd[B_*T_];

__device__ __forceinline__ float tf32r(float x) {
    uint32_t r;
    asm("cvt.rna.tf32.f32 %0, %1;" : "=r"(r) : "f"(x));
    return __uint_as_float(r);
}

__device__ __forceinline__ void cp16g(void* dst, const void* src) {
    unsigned d = (unsigned)__cvta_generic_to_shared(dst);
    asm volatile("cp.async.cg.shared.global [%0], [%1], 16;\n" :: "r"(d), "l"(src));
}

#define MMA_F16(d0,d1,d2,d3,a0,a1,a2,a3,b0,b1) \
    asm volatile("mma.sync.aligned.m16n8k16.row.col.f32.f16.f16.f32 " \
                 "{%0,%1,%2,%3},{%4,%5,%6,%7},{%8,%9},{%0,%1,%2,%3};" \
                 : "+f"(d0), "+f"(d1), "+f"(d2), "+f"(d3) \
                 : "r"(a0), "r"(a1), "r"(a2), "r"(a3), "r"(b0), "r"(b1))

#define MMA_TF32(d0,d1,d2,d3,a0,a1,a2,a3,b0,b1) \
    asm volatile("mma.sync.aligned.m16n8k8.row.col.f32.tf32.tf32.f32 " \
                 "{%0,%1,%2,%3},{%4,%5,%6,%7},{%8,%9},{%0,%1,%2,%3};" \
                 : "+f"(d0), "+f"(d1), "+f"(d2), "+f"(d3) \
                 : "r"(a0), "r"(a1), "r"(a2), "r"(a3), "r"(b0), "r"(b1))

// ---------------------------------------------------------------------------
// prep_w2: one block per m. W16[m][k]=fp16(raw[m][k]*gamma[k]);
//          w2g1[m]=sum_k W16; w2b[m]=raw·beta
// ---------------------------------------------------------------------------
__global__ void prep_w2(const float* __restrict__ wq, const float* __restrict__ wk,
                        const float* __restrict__ wv, const float* __restrict__ wproj,
                        const float* __restrict__ gamma, const float* __restrict__ beta)
{
    int m = blockIdx.x;
    int tid = threadIdx.x;
    float lg = 0.f, lb = 0.f;
    #pragma unroll
    for (int jj = 0; jj < 2; jj++) {
        int j = jj * 256 + tid;
        float acc = 0.f;
        if (m < 512) {
            #pragma unroll 4
            for (int o = 0; o < 512; o++)
                acc += wq[o*512 + m] * wk[o*512 + j];
        } else {
            int i = m - 512;
            #pragma unroll 4
            for (int c = 0; c < 512; c++)
                acc += wproj[i*512 + c] * wv[c*512 + j];
        }
        __half wh = __float2half(acc * gamma[j]);
        d_W16[(size_t)m * 512 + j] = wh;
        lg += __half2float(wh);
        lb += acc * beta[j];
    }
    __shared__ float red[16];
    #pragma unroll
    for (int o = 16; o > 0; o >>= 1) {
        lg += __shfl_down_sync(0xffffffffu, lg, o);
        lb += __shfl_down_sync(0xffffffffu, lb, o);
    }
    int w = tid >> 5;
    if ((tid & 31) == 0) { red[w] = lg; red[8 + w] = lb; }
    __syncthreads();
    if (tid == 0) {
        float G = 0.f, Bv = 0.f;
        for (int k = 0; k < 8; k++) { G += red[k]; Bv += red[8 + k]; }
        d_w2g1[m] = G;
        d_w2b[m]  = Bv;
    }
}

// ---------------------------------------------------------------------------
// conv_x16: x [b][c][n] fp32 -> d_x16 [b][n][c] fp16.  64c x 64n smem tiles.
// ---------------------------------------------------------------------------
__global__ void conv_x16(const float* __restrict__ x)
{
    __shared__ float sT[64][65];
    int b   = blockIdx.z;
    int c0  = blockIdx.y * 64;
    int n0t = blockIdx.x * 64;
    int tid = threadIdx.x;
    const float* xb = x + (size_t)b * C_ * NCOL;
    #pragma unroll
    for (int r = 0; r < 4; r++) {
        int flat = r * 256 + tid;           // 0..1023 float4 units
        int cr = flat >> 4, nq = flat & 15;
        float4 v = *reinterpret_cast<const float4*>(
            xb + (size_t)(c0 + cr) * NCOL + n0t + nq * 4);
        sT[cr][nq*4+0] = v.x; sT[cr][nq*4+1] = v.y;
        sT[cr][nq*4+2] = v.z; sT[cr][nq*4+3] = v.w;
    }
    __syncthreads();
    int nr = tid >> 2, cq = tid & 3;        // 64 n-rows x 4 chunks of 16c
    uint32_t pk[8];
    #pragma unroll
    for (int j = 0; j < 8; j++) {
        __half2 h2 = __floats2half2_rn(sT[cq*16 + j*2][nr], sT[cq*16 + j*2 + 1][nr]);
        pk[j] = *reinterpret_cast<uint32_t*>(&h2);
    }
    __half* dst = d_x16 + ((size_t)b * NCOL + n0t + nr) * 512 + c0 + cq * 16;
    *reinterpret_cast<uint4*>(dst)     = make_uint4(pk[0], pk[1], pk[2], pk[3]);
    *reinterpret_cast<uint4*>(dst + 8) = make_uint4(pk[4], pk[5], pk[6], pk[7]);
}

// ---------------------------------------------------------------------------
// LayerNorm stats
// ---------------------------------------------------------------------------
__global__ void ln_stats(const float* __restrict__ x)
{
    int g = blockIdx.x;
    int b = g >> 5, t = g & 31;
    const float4* base = reinterpret_cast<const float4*>(
        x + ((size_t)(b * C_) * T_ + t) * HW_);
    float s = 0.f, ss = 0.f;
    for (int i = threadIdx.x; i < 512*256; i += blockDim.x) {
        int c = i >> 8, hw4 = i & 255;
        float4 v = base[(size_t)c * (T_*HW_/4) + hw4];
        s  += v.x + v.y + v.z + v.w;
        ss += v.x*v.x + v.y*v.y + v.z*v.z + v.w*v.w;
    }
    __shared__ float sm[64];
    #pragma unroll
    for (int o = 16; o > 0; o >>= 1) {
        s  += __shfl_down_sync(0xffffffffu, s,  o);
        ss += __shfl_down_sync(0xffffffffu, ss, o);
    }
    int w = threadIdx.x >> 5;
    if ((threadIdx.x & 31) == 0) { sm[w] = s; sm[32 + w] = ss; }
    __syncthreads();
    if (threadIdx.x == 0) {
        float S = 0.f, SS = 0.f;
        int nw = blockDim.x >> 5;
        for (int k = 0; k < nw; k++) { S += sm[k]; SS += sm[32 + k]; }
        float invn = 1.f / (float)(C_ * HW_);
        float m   = S * invn;
        float var = SS * invn - m * m;
        d_mean[g] = m;
        d_rstd[g] = rsqrtf(var + 1e-6f);
    }
}

// ---------------------------------------------------------------------------
// fp16 GEMM: y = W16·x16^T per batch; epilogue u/vp = rstd·y + bias (fp32).
// Block 128x128, 4 warps (2x2), warp tile 64x64. 4-stage cp.async, k=32/stage.
// smem rows: 32 halfs + 8 pad = 40 halfs (20 words) -> conflict-free frags.
// ---------------------------------------------------------------------------
#define AROW 40                  // halfs per k-row
#define STH  (128*AROW)          // 5120 halfs per A or B stage tile
#define STAGEH (2*STH)           // 10240 halfs per stage
#define GEMM_SMEM (4*STAGEH*2)   // bytes = 81920

__global__ __launch_bounds__(128, 2) void gemm_uv_f16()
{
    extern __shared__ __half smh[];
    int b  = blockIdx.z;
    int m0 = blockIdx.x * 128;       // m fastest -> x16 tile L2 reuse
    int n0 = blockIdx.y * 128;
    const __half* xb = d_x16 + (size_t)b * NCOL * 512;
    int tid  = threadIdx.x;
    int lane = tid & 31;
    int w    = tid >> 5;
    int warpM = w >> 1, warpN = w & 1;
    int g = lane >> 2, tq = lane & 3;
    int am = warpM * 64 + g;
    int bn = warpN * 64 + g;

    float acc[4][8][4];
    #pragma unroll
    for (int i = 0; i < 4; i++)
        #pragma unroll
        for (int j = 0; j < 8; j++)
            #pragma unroll
            for (int r = 0; r < 4; r++) acc[i][j][r] = 0.f;

    auto load_stage = [&](int k0, int buf) {
        __half* As = smh + buf * STAGEH;
        __half* Bs = As + STH;
        #pragma unroll
        for (int r = 0; r < 4; r++) {
            int ch = r * 128 + tid;          // 0..511
            int row = ch >> 2;               // 0..127
            int q   = ch & 3;                // 16B quad within 32-half chunk
            cp16g(As + row * AROW + q * 8, &d_W16[(size_t)(m0 + row) * 512 + k0 + q * 8]);
            cp16g(Bs + row * AROW + q * 8, &xb[(size_t)(n0 + row) * 512 + k0 + q * 8]);
        }
    };

    #pragma unroll
    for (int p = 0; p < 3; p++) {
        load_stage(p * 32, p);
        asm volatile("cp.async.commit_group;\n");
    }

    for (int it = 0; it < 16; it++) {
        asm volatile("cp.async.wait_group 2;\n");
        __syncthreads();

        const uint32_t* Asw = reinterpret_cast<const uint32_t*>(smh + (it & 3) * STAGEH);
        const uint32_t* Bsw = Asw + STH / 2;

        #pragma unroll
        for (int ks = 0; ks < 16; ks += 8) {   // two k16 halves (word offset)
            uint32_t a[4][4], bq[8][2];
            #pragma unroll
            for (int mf = 0; mf < 4; mf++) {
                int r0 = (am + mf * 16) * 20 + ks + tq;
                int r1 = (am + mf * 16 + 8) * 20 + ks + tq;
                a[mf][0] = Asw[r0];
                a[mf][1] = Asw[r1];
                a[mf][2] = Asw[r0 + 4];
                a[mf][3] = Asw[r1 + 4];
            }
            #pragma unroll
            for (int nf = 0; nf < 8; nf++) {
                int rb = (bn + nf * 8) * 20 + ks + tq;
                bq[nf][0] = Bsw[rb];
                bq[nf][1] = Bsw[rb + 4];
            }
            #pragma unroll
            for (int mf = 0; mf < 4; mf++)
                #pragma unroll
                for (int nf = 0; nf < 8; nf++)
                    MMA_F16(acc[mf][nf][0], acc[mf][nf][1], acc[mf][nf][2], acc[mf][nf][3],
                            a[mf][0], a[mf][1], a[mf][2], a[mf][3],
                            bq[nf][0], bq[nf][1]);
        }
        if (it + 3 < 16)
            load_stage((it + 3) * 32, (it + 3) & 3);
        asm volatile("cp.async.commit_group;\n");
    }

    // epilogue: LN correction + tf32 rounding, fp32 outputs
    int tcol = blockIdx.y >> 3;
    int gidx = b * 32 + tcol;
    float rstdv = d_rstd[gidx];
    float rm    = rstdv * d_mean[gidx];
    bool isU = (m0 < 512);
    float* outbase = isU ? (d_u  + (size_t)(b * 512 + m0)       * NCOL)
                         : (d_vp + (size_t)(b * 512 + m0 - 512) * NCOL);
    #pragma unroll
    for (int mf = 0; mf < 4; mf++) {
        int mrow = warpM * 64 + mf * 16 + g;
        int mg0 = m0 + mrow, mg1 = m0 + mrow + 8;
        float bias0 = d_w2b[mg0] - rm * d_w2g1[mg0];
        float bias1 = d_w2b[mg1] - rm * d_w2g1[mg1];
        #pragma unroll
        for (int nf = 0; nf < 8; nf++) {
            int ncol = n0 + warpN * 64 + nf * 8 + tq * 2;
            float2 lo = make_float2(tf32r(rstdv * acc[mf][nf][0] + bias0),
                                    tf32r(rstdv * acc[mf][nf][1] + bias0));
            float2 hi = make_float2(tf32r(rstdv * acc[mf][nf][2] + bias1),
                                    tf32r(rstdv * acc[mf][nf][3] + bias1));
            *reinterpret_cast<float2*>(outbase + (size_t)mrow * NCOL + ncol)       = lo;
            *reinterpret_cast<float2*>(outbase + (size_t)(mrow + 8) * NCOL + ncol) = hi;
        }
    }
}

// ---------------------------------------------------------------------------
// Tensor-core attention + residual, LN folded (unchanged from R7).
// ---------------------------------------------------------------------------
#define HS_CSTR 296
#define GS_TSTR 292
#define VP_SSTR 168
#define OS_TSTR 164
#define ATTN_SMEM_FLOATS (9344 + 5376 + 5248)   // 19968 floats

__global__ __launch_bounds__(256, 2) void attn_mma(const float* __restrict__ x,
                                                   const float* __restrict__ gamma,
                                                   const float* __restrict__ beta,
                                                   float* __restrict__ out)
{
    extern __shared__ float sm[];
    float* Hs  = sm;
    float* Us  = sm + 4736;
    float* Gs  = sm;
    float* VPs = sm + 9344;
    float* Os  = sm + 14720;
    float* gus = sm + 14720;
    float* bus = sm + 14976;
    float* smG = sm + 15800;
    float* smB = sm + 15816;

    int blk = blockIdx.x;
    int b   = blk >> 7;
    int hw0 = (blk & 127) * 8;
    int tid  = threadIdx.x;
    int lane = tid & 31;
    int px   = tid >> 5;
    int g = lane >> 2, tq = lane & 3;
    const size_t pixbase = (size_t)b * C_ * T_ * HW_ + hw0;
    const float* xg = x    + pixbase;
    const float* ug = d_u  + pixbase;
    const float* vg = d_vp + pixbase;

    int s_ = tid >> 3, px_ = tid & 7;
    float gu = 0.f, bu = 0.f;

    float acc1[2][4][4];
    #pragma unroll
    for (int i = 0; i < 2; i++)
        #pragma unroll
        for (int j = 0; j < 4; j++)
            #pragma unroll
            for (int r = 0; r < 4; r++) acc1[i][j][r] = 0.f;

    float4 ph[4], pu[4];
    auto prefetch1 = [&](int c0) {
        #pragma unroll
        for (int r = 0; r < 4; r++) {
            int flat = r * 256 + tid;
            int pp = flat & 1;
            int t  = (flat >> 1) & 31;
            int c  = flat >> 6;
            size_t go = ((size_t)(c0 + c) * 32 + t) * 1024 + pp * 4;
            ph[r] = *reinterpret_cast<const float4*>(xg + go);
            pu[r] = *reinterpret_cast<const float4*>(ug + go);
        }
    };
    auto store1 = [&](int c0) {
        #pragma unroll
        for (int r = 0; r < 4; r++) {
            int flat = r * 256 + tid;
            int pp = flat & 1;
            int t  = (flat >> 1) & 31;
            int c  = flat >> 6;
            float gam = gamma[c0 + c];
            int so = c * HS_CSTR + t * 9 + pp * 4;
            Hs[so] = gam*ph[r].x; Hs[so+1] = gam*ph[r].y;
            Hs[so+2] = gam*ph[r].z; Hs[so+3] = gam*ph[r].w;
            Us[so] = pu[r].x; Us[so+1] = pu[r].y; Us[so+2] = pu[r].z; Us[so+3] = pu[r].w;
        }
    };

    prefetch1(0);
    for (int c0 = 0; c0 < 512; c0 += 16) {
        store1(c0);
        if (tid < 16)       smG[tid]      = gamma[c0 + tid];
        else if (tid < 32)  smB[tid - 16] = beta[c0 + tid - 16];
        __syncthreads();
        if (c0 + 16 < 512) prefetch1(c0 + 16);

        const uint32_t* Hu = reinterpret_cast<const uint32_t*>(Hs);
        const uint32_t* Uu = reinterpret_cast<const uint32_t*>(Us);
        #pragma unroll
        for (int kk = 0; kk < 16; kk += 8) {
            uint32_t a[2][4], bq[4][2];
            #pragma unroll
            for (int mf = 0; mf < 2; mf++) {
                int base = (kk + tq) * HS_CSTR + (mf * 16 + g) * 9 + px;
                a[mf][0] = Hu[base];
                a[mf][1] = Hu[base + 72];
                a[mf][2] = Hu[base + 4 * HS_CSTR];
                a[mf][3] = Hu[base + 4 * HS_CSTR + 72];
            }
            #pragma unroll
            for (int nf = 0; nf < 4; nf++) {
                int base = (kk + tq) * HS_CSTR + (nf * 8 + g) * 9 + px;
                bq[nf][0] = Uu[base];
                bq[nf][1] = Uu[base + 4 * HS_CSTR];
            }
            #pragma unroll
            for (int mf = 0; mf < 2; mf++)
                #pragma unroll
                for (int nf = 0; nf < 4; nf++)
                    MMA_TF32(acc1[mf][nf][0], acc1[mf][nf][1], acc1[mf][nf][2], acc1[mf][nf][3],
                             a[mf][0], a[mf][1], a[mf][2], a[mf][3],
                             bq[nf][0], bq[nf][1]);
        }
        #pragma unroll
        for (int c = 0; c < 16; c++) {
            float uv = Us[c * HS_CSTR + s_ * 9 + px_];
            gu += smG[c] * uv;
            bu += smB[c] * uv;
        }
        __syncthreads();
    }

    gus[s_ * 8 + px_] = gu;
    bus[s_ * 8 + px_] = bu;
    __syncthreads();

    const float scale = 0.044194173824159216f;
    #pragma unroll
    for (int mf = 0; mf < 2; mf++) {
        int t0 = mf * 16 + g, t1 = t0 + 8;
        float r0 = d_rstd[b*32 + t0], m0v = d_mean[b*32 + t0];
        float r1 = d_rstd[b*32 + t1], m1v = d_mean[b*32 + t1];
        #pragma unroll
        for (int nf = 0; nf < 4; nf++) {
            int s0 = nf * 8 + tq * 2, s1 = s0 + 1;
            float gu0 = gus[s0*8 + px], bu0 = bus[s0*8 + px];
            float gu1 = gus[s1*8 + px], bu1 = bus[s1*8 + px];
            Gs[t0 * GS_TSTR + s0 * 9 + px] = (r0*(acc1[mf][nf][0] - m0v*gu0) + bu0) * scale;
            Gs[t0 * GS_TSTR + s1 * 9 + px] = (r0*(acc1[mf][nf][1] - m0v*gu1) + bu1) * scale;
            Gs[t1 * GS_TSTR + s0 * 9 + px] = (r1*(acc1[mf][nf][2] - m1v*gu0) + bu0) * scale;
            Gs[t1 * GS_TSTR + s1 * 9 + px] = (r1*(acc1[mf][nf][3] - m1v*gu1) + bu1) * scale;
        }
    }
    __syncthreads();

    {
        int pxs = tid & 7;
        int t   = tid >> 3;
        int gb  = t * GS_TSTR + pxs;
        float mx = -1e30f;
        for (int s = 0; s <= t; s++) mx = fmaxf(mx, Gs[gb + s * 9]);
        float Z = 0.f;
        for (int s = 0; s <= t; s++) Z += __expf(Gs[gb + s * 9] - mx);
        float iz = 1.f / Z;
        for (int s = 0; s < 32; s++) {
            float v = (s <= t) ? __expf(Gs[gb + s * 9] - mx) * iz : 0.f;
            Gs[gb + s * 9] = tf32r(v);
        }
    }
    __syncthreads();

    const uint32_t* Gu = reinterpret_cast<const uint32_t*>(Gs);
    float4 pv[4];
    auto prefetch4 = [&](int oc) {
        #pragma unroll
        for (int r = 0; r < 4; r++) {
            int flat = r * 256 + tid;
            int pp = flat & 1;
            int s  = (flat >> 1) & 31;
            int o  = flat >> 6;
            size_t go = ((size_t)(oc + o) * 32 + s) * 1024 + pp * 4;
            pv[r] = *reinterpret_cast<const float4*>(vg + go);
        }
    };

    prefetch4(0);
    for (int oc = 0; oc < 512; oc += 16) {
        #pragma unroll
        for (int r = 0; r < 4; r++) {
            int flat = r * 256 + tid;
            int pp = flat & 1;
            int s  = (flat >> 1) & 31;
            int o  = flat >> 6;
            int so = s * VP_SSTR + o * 9 + pp * 4;
            VPs[so] = pv[r].x; VPs[so+1] = pv[r].y; VPs[so+2] = pv[r].z; VPs[so+3] = pv[r].w;
        }
        __syncthreads();
        if (oc + 16 < 512) prefetch4(oc + 16);

        float acc2[2][2][4];
        #pragma unroll
        for (int i = 0; i < 2; i++)
            #pragma unroll
            for (int j = 0; j < 2; j++)
                #pragma unroll
                for (int r = 0; r < 4; r++) acc2[i][j][r] = 0.f;

        const uint32_t* Vu = reinterpret_cast<const uint32_t*>(VPs);
        #pragma unroll
        for (int kk = 0; kk < 32; kk += 8) {
            uint32_t a[2][4], bq[2][2];
            #pragma unroll
            for (int mf = 0; mf < 2; mf++) {
                int base = (mf * 16 + g) * GS_TSTR + (kk + tq) * 9 + px;
                a[mf][0] = Gu[base];
                a[mf][1] = Gu[base + 8 * GS_TSTR];
                a[mf][2] = Gu[base + 36];
                a[mf][3] = Gu[base + 8 * GS_TSTR + 36];
            }
            #pragma unroll
            for (int nf = 0; nf < 2; nf++) {
                int base = (kk + tq) * VP_SSTR + (nf * 8 + g) * 9 + px;
                bq[nf][0] = Vu[base];
                bq[nf][1] = Vu[base + 4 * VP_SSTR];
            }
            #pragma unroll
            for (int mf = 0; mf < 2; mf++)
                #pragma unroll
                for (int nf = 0; nf < 2; nf++)
                    MMA_TF32(acc2[mf][nf][0], acc2[mf][nf][1], acc2[mf][nf][2], acc2[mf][nf][3],
                             a[mf][0], a[mf][1], a[mf][2], a[mf][3],
                             bq[nf][0], bq[nf][1]);
        }

        #pragma unroll
        for (int mf = 0; mf < 2; mf++) {
            #pragma unroll
            for (int nf = 0; nf < 2; nf++) {
                int t = mf * 16 + g;
                int o = nf * 8 + tq * 2;
                Os[t * OS_TSTR + o * 10 + px]             = acc2[mf][nf][0];
                Os[t * OS_TSTR + (o + 1) * 10 + px]       = acc2[mf][nf][1];
                Os[(t + 8) * OS_TSTR + o * 10 + px]       = acc2[mf][nf][2];
                Os[(t + 8) * OS_TSTR + (o + 1) * 10 + px] = acc2[mf][nf][3];
            }
        }
        __syncthreads();

        #pragma unroll
        for (int r = 0; r < 4; r++) {
            int flat = r * 256 + tid;
            int pp = flat & 1;
            int t  = (flat >> 1) & 31;
            int o  = flat >> 6;
            size_t gg = pixbase + ((size_t)(oc + o) * 32 + t) * 1024 + pp * 4;
            float4 xv = *reinterpret_cast<const float4*>(x + gg);
            int so = t * OS_TSTR + o * 10 + pp * 4;
            float4 ov;
            ov.x = Os[so]     + xv.x;
            ov.y = Os[so + 1] + xv.y;
            ov.z = Os[so + 2] + xv.z;
            ov.w = Os[so + 3] + xv.w;
            *reinterpret_cast<float4*>(out + gg) = ov;
        }
        __syncthreads();
    }
}

// ---------------------------------------------------------------------------
extern "C" void kernel_launch(void* const* d_in, const int* in_sizes, int n_in,
                              void* d_out, int out_size)
{
    const float* x     = (const float*)d_in[0];
    const float* gamma = (const float*)d_in[1];
    const float* beta  = (const float*)d_in[2];
    const float* wq    = (const float*)d_in[3];
    const float* wk    = (const float*)d_in[4];
    const float* wv    = (const float*)d_in[5];
    const float* wproj = (const float*)d_in[6];
    float* out = (float*)d_out;

    cudaFuncSetAttribute(gemm_uv_f16, cudaFuncAttributeMaxDynamicSharedMemorySize,
                         GEMM_SMEM);
    cudaFuncSetAttribute(attn_mma, cudaFuncAttributeMaxDynamicSharedMemorySize,
                         ATTN_SMEM_FLOATS * 4);

    prep_w2<<<1024, 256>>>(wq, wk, wv, wproj, gamma, beta);
    conv_x16<<<dim3(512, 8, B_), 256>>>(x);
    ln_stats<<<128, 1024>>>(x);
    gemm_uv_f16<<<dim3(8, 256, B_), 128, GEMM_SMEM>>>();
    attn_mma<<<512, 256, ATTN_SMEM_FLOATS * 4>>>(x, gamma, beta, out);
}

// round 9
// speedup vs baseline: 3.1391x; 1.0702x over previous
#include <cuda_runtime.h>
#include <cuda_fp16.h>
#include <math.h>
#include <stdint.h>

#define B_   4
#define C_   512
#define T_   32
#define HW_  1024
#define NCOL (T_*HW_)            // 32768 columns per batch
#define TOT  (B_*C_*T_*HW_)

// Scratch
__device__ __half d_x16[TOT];      // x transposed+fp16: [b][n][c] (n = t*1024+hw)
__device__ __half d_W16[1024*512]; // W2G = W2·diag(gamma), [m][k], fp16
__device__ __half d_u16[TOT];      // u  (fp16, [b][c][n])
__device__ __half d_vp16[TOT];     // v' (fp16, [b][c][n])
__device__ float  d_w2g1[1024];    // row sums of W16
__device__ float  d_w2b[1024];     // W2·beta
__device__ float  d_psum[16384];   // per-block partial sums (conv_x16)
__device__ float  d_psum2[16384];
__device__ float  d_mean[B_*T_];
__device__ float  d_rstd[B_*T_];

__device__ __forceinline__ float tf32r(float x) {
    uint32_t r;
    asm("cvt.rna.tf32.f32 %0, %1;" : "=r"(r) : "f"(x));
    return __uint_as_float(r);
}

__device__ __forceinline__ void cp16g(void* dst, const void* src) {
    unsigned d = (unsigned)__cvta_generic_to_shared(dst);
    asm volatile("cp.async.cg.shared.global [%0], [%1], 16;\n" :: "r"(d), "l"(src));
}

#define MMA_F16(d0,d1,d2,d3,a0,a1,a2,a3,b0,b1) \
    asm volatile("mma.sync.aligned.m16n8k16.row.col.f32.f16.f16.f32 " \
                 "{%0,%1,%2,%3},{%4,%5,%6,%7},{%8,%9},{%0,%1,%2,%3};" \
                 : "+f"(d0), "+f"(d1), "+f"(d2), "+f"(d3) \
                 : "r"(a0), "r"(a1), "r"(a2), "r"(a3), "r"(b0), "r"(b1))

#define MMA_TF32(d0,d1,d2,d3,a0,a1,a2,a3,b0,b1) \
    asm volatile("mma.sync.aligned.m16n8k8.row.col.f32.tf32.tf32.f32 " \
                 "{%0,%1,%2,%3},{%4,%5,%6,%7},{%8,%9},{%0,%1,%2,%3};" \
                 : "+f"(d0), "+f"(d1), "+f"(d2), "+f"(d3) \
                 : "r"(a0), "r"(a1), "r"(a2), "r"(a3), "r"(b0), "r"(b1))

// ---------------------------------------------------------------------------
// prep_w2: one block per m. W16[m][k]=fp16(raw[m][k]*gamma[k]);
//          w2g1[m]=sum_k W16; w2b[m]=raw·beta
// ---------------------------------------------------------------------------
__global__ void prep_w2(const float* __restrict__ wq, const float* __restrict__ wk,
                        const float* __restrict__ wv, const float* __restrict__ wproj,
                        const float* __restrict__ gamma, const float* __restrict__ beta)
{
    int m = blockIdx.x;
    int tid = threadIdx.x;
    float lg = 0.f, lb = 0.f;
    #pragma unroll
    for (int jj = 0; jj < 2; jj++) {
        int j = jj * 256 + tid;
        float acc = 0.f;
        if (m < 512) {
            #pragma unroll 4
            for (int o = 0; o < 512; o++)
                acc += wq[o*512 + m] * wk[o*512 + j];
        } else {
            int i = m - 512;
            #pragma unroll 4
            for (int c = 0; c < 512; c++)
                acc += wproj[i*512 + c] * wv[c*512 + j];
        }
        __half wh = __float2half(acc * gamma[j]);
        d_W16[(size_t)m * 512 + j] = wh;
        lg += __half2float(wh);
        lb += acc * beta[j];
    }
    __shared__ float red[16];
    #pragma unroll
    for (int o = 16; o > 0; o >>= 1) {
        lg += __shfl_down_sync(0xffffffffu, lg, o);
        lb += __shfl_down_sync(0xffffffffu, lb, o);
    }
    int w = tid >> 5;
    if ((tid & 31) == 0) { red[w] = lg; red[8 + w] = lb; }
    __syncthreads();
    if (tid == 0) {
        float G = 0.f, Bv = 0.f;
        for (int k = 0; k < 8; k++) { G += red[k]; Bv += red[8 + k]; }
        d_w2g1[m] = G;
        d_w2b[m]  = Bv;
    }
}

// ---------------------------------------------------------------------------
// conv_x16: x [b][c][n] fp32 -> d_x16 [b][n][c] fp16, 64c x 64n smem tiles,
// PLUS per-block LN partial sums (each block covers a single (b,t)).
// ---------------------------------------------------------------------------
__global__ void conv_x16(const float* __restrict__ x)
{
    __shared__ float sT[64][65];
    __shared__ float rsum[8], rsum2[8];
    int b   = blockIdx.z;
    int c0  = blockIdx.y * 64;
    int n0t = blockIdx.x * 64;
    int tid = threadIdx.x;
    const float* xb = x + (size_t)b * C_ * NCOL;
    float s = 0.f, ss = 0.f;
    #pragma unroll
    for (int r = 0; r < 4; r++) {
        int flat = r * 256 + tid;           // 0..1023 float4 units
        int cr = flat >> 4, nq = flat & 15;
        float4 v = *reinterpret_cast<const float4*>(
            xb + (size_t)(c0 + cr) * NCOL + n0t + nq * 4);
        sT[cr][nq*4+0] = v.x; sT[cr][nq*4+1] = v.y;
        sT[cr][nq*4+2] = v.z; sT[cr][nq*4+3] = v.w;
        s  += v.x + v.y + v.z + v.w;
        ss += v.x*v.x + v.y*v.y + v.z*v.z + v.w*v.w;
    }
    #pragma unroll
    for (int o = 16; o > 0; o >>= 1) {
        s  += __shfl_down_sync(0xffffffffu, s,  o);
        ss += __shfl_down_sync(0xffffffffu, ss, o);
    }
    if ((tid & 31) == 0) { rsum[tid >> 5] = s; rsum2[tid >> 5] = ss; }
    __syncthreads();
    if (tid == 0) {
        float S = 0.f, SS = 0.f;
        #pragma unroll
        for (int k = 0; k < 8; k++) { S += rsum[k]; SS += rsum2[k]; }
        int t = blockIdx.x >> 4, nIn = blockIdx.x & 15;
        int pid = ((b * 32 + t) * 8 + blockIdx.y) * 16 + nIn;
        d_psum[pid]  = S;
        d_psum2[pid] = SS;
    }
    int nr = tid >> 2, cq = tid & 3;        // 64 n-rows x 4 chunks of 16c
    uint32_t pk[8];
    #pragma unroll
    for (int j = 0; j < 8; j++) {
        __half2 h2 = __floats2half2_rn(sT[cq*16 + j*2][nr], sT[cq*16 + j*2 + 1][nr]);
        pk[j] = *reinterpret_cast<uint32_t*>(&h2);
    }
    __half* dst = d_x16 + ((size_t)b * NCOL + n0t + nr) * 512 + c0 + cq * 16;
    *reinterpret_cast<uint4*>(dst)     = make_uint4(pk[0], pk[1], pk[2], pk[3]);
    *reinterpret_cast<uint4*>(dst + 8) = make_uint4(pk[4], pk[5], pk[6], pk[7]);
}

// ---------------------------------------------------------------------------
// reduce_stats: 128 blocks (one per (b,t)), sum 128 partials -> mean/rstd
// ---------------------------------------------------------------------------
__global__ void reduce_stats()
{
    int g = blockIdx.x;
    int tid = threadIdx.x;                  // 128 threads
    float s  = d_psum[g * 128 + tid];
    float ss = d_psum2[g * 128 + tid];
    #pragma unroll
    for (int o = 16; o > 0; o >>= 1) {
        s  += __shfl_down_sync(0xffffffffu, s,  o);
        ss += __shfl_down_sync(0xffffffffu, ss, o);
    }
    __shared__ float sm[8];
    if ((tid & 31) == 0) { sm[tid >> 5] = s; sm[4 + (tid >> 5)] = ss; }
    __syncthreads();
    if (tid == 0) {
        float S = sm[0] + sm[1] + sm[2] + sm[3];
        float SS = sm[4] + sm[5] + sm[6] + sm[7];
        float invn = 1.f / (float)(C_ * HW_);
        float m = S * invn;
        float var = SS * invn - m * m;
        d_mean[g] = m;
        d_rstd[g] = rsqrtf(var + 1e-6f);
    }
}

// ---------------------------------------------------------------------------
// fp16 GEMM: y = W16·x16^T per batch; epilogue u/vp = fp16(rstd·y + bias).
// Block 128x128, 4 warps (2x2), warp tile 64x64. 4-stage cp.async, k=32/stage.
// ---------------------------------------------------------------------------
#define AROW 40                  // halfs per k-row (32 + 8 pad)
#define STH  (128*AROW)          // 5120 halfs per A or B stage tile
#define STAGEH (2*STH)           // 10240 halfs per stage
#define GEMM_SMEM (4*STAGEH*2)   // bytes = 81920

__global__ __launch_bounds__(128, 2) void gemm_uv_f16()
{
    extern __shared__ __half smh[];
    int b  = blockIdx.z;
    int m0 = blockIdx.x * 128;
    int n0 = blockIdx.y * 128;
    const __half* xb = d_x16 + (size_t)b * NCOL * 512;
    int tid  = threadIdx.x;
    int lane = tid & 31;
    int w    = tid >> 5;
    int warpM = w >> 1, warpN = w & 1;
    int g = lane >> 2, tq = lane & 3;
    int am = warpM * 64 + g;
    int bn = warpN * 64 + g;

    float acc[4][8][4];
    #pragma unroll
    for (int i = 0; i < 4; i++)
        #pragma unroll
        for (int j = 0; j < 8; j++)
            #pragma unroll
            for (int r = 0; r < 4; r++) acc[i][j][r] = 0.f;

    auto load_stage = [&](int k0, int buf) {
        __half* As = smh + buf * STAGEH;
        __half* Bs = As + STH;
        #pragma unroll
        for (int r = 0; r < 4; r++) {
            int ch = r * 128 + tid;          // 0..511
            int row = ch >> 2;
            int q   = ch & 3;
            cp16g(As + row * AROW + q * 8, &d_W16[(size_t)(m0 + row) * 512 + k0 + q * 8]);
            cp16g(Bs + row * AROW + q * 8, &xb[(size_t)(n0 + row) * 512 + k0 + q * 8]);
        }
    };

    #pragma unroll
    for (int p = 0; p < 3; p++) {
        load_stage(p * 32, p);
        asm volatile("cp.async.commit_group;\n");
    }

    for (int it = 0; it < 16; it++) {
        asm volatile("cp.async.wait_group 2;\n");
        __syncthreads();

        const uint32_t* Asw = reinterpret_cast<const uint32_t*>(smh + (it & 3) * STAGEH);
        const uint32_t* Bsw = Asw + STH / 2;

        #pragma unroll
        for (int ks = 0; ks < 16; ks += 8) {
            uint32_t a[4][4], bq[8][2];
            #pragma unroll
            for (int mf = 0; mf < 4; mf++) {
                int r0 = (am + mf * 16) * 20 + ks + tq;
                int r1 = (am + mf * 16 + 8) * 20 + ks + tq;
                a[mf][0] = Asw[r0];
                a[mf][1] = Asw[r1];
                a[mf][2] = Asw[r0 + 4];
                a[mf][3] = Asw[r1 + 4];
            }
            #pragma unroll
            for (int nf = 0; nf < 8; nf++) {
                int rb = (bn + nf * 8) * 20 + ks + tq;
                bq[nf][0] = Bsw[rb];
                bq[nf][1] = Bsw[rb + 4];
            }
            #pragma unroll
            for (int mf = 0; mf < 4; mf++)
                #pragma unroll
                for (int nf = 0; nf < 8; nf++)
                    MMA_F16(acc[mf][nf][0], acc[mf][nf][1], acc[mf][nf][2], acc[mf][nf][3],
                            a[mf][0], a[mf][1], a[mf][2], a[mf][3],
                            bq[nf][0], bq[nf][1]);
        }
        if (it + 3 < 16)
            load_stage((it + 3) * 32, (it + 3) & 3);
        asm volatile("cp.async.commit_group;\n");
    }

    // epilogue: LN correction, fp16 outputs
    int tcol = blockIdx.y >> 3;
    int gidx = b * 32 + tcol;
    float rstdv = d_rstd[gidx];
    float rm    = rstdv * d_mean[gidx];
    bool isU = (m0 < 512);
    __half* outb = isU ? (d_u16  + (size_t)(b * 512 + m0)       * NCOL)
                       : (d_vp16 + (size_t)(b * 512 + m0 - 512) * NCOL);
    #pragma unroll
    for (int mf = 0; mf < 4; mf++) {
        int mrow = warpM * 64 + mf * 16 + g;
        int mg0 = m0 + mrow, mg1 = m0 + mrow + 8;
        float bias0 = d_w2b[mg0] - rm * d_w2g1[mg0];
        float bias1 = d_w2b[mg1] - rm * d_w2g1[mg1];
        #pragma unroll
        for (int nf = 0; nf < 8; nf++) {
            int ncol = n0 + warpN * 64 + nf * 8 + tq * 2;
            __half2 lo = __floats2half2_rn(rstdv * acc[mf][nf][0] + bias0,
                                           rstdv * acc[mf][nf][1] + bias0);
            __half2 hi = __floats2half2_rn(rstdv * acc[mf][nf][2] + bias1,
                                           rstdv * acc[mf][nf][3] + bias1);
            *reinterpret_cast<__half2*>(outb + (size_t)mrow * NCOL + ncol)       = lo;
            *reinterpret_cast<__half2*>(outb + (size_t)(mrow + 8) * NCOL + ncol) = hi;
        }
    }
}

// ---------------------------------------------------------------------------
// Tensor-core attention + residual, LN folded. u/vp read as fp16;
// phase-4 residual x loads hoisted ahead of the MMA section.
// ---------------------------------------------------------------------------
#define HS_CSTR 296
#define GS_TSTR 292
#define VP_SSTR 168
#define OS_TSTR 164
#define ATTN_SMEM_FLOATS (9344 + 5376 + 5248)   // 19968 floats

__global__ __launch_bounds__(256, 2) void attn_mma(const float* __restrict__ x,
                                                   const float* __restrict__ gamma,
                                                   const float* __restrict__ beta,
                                                   float* __restrict__ out)
{
    extern __shared__ float sm[];
    float* Hs  = sm;
    float* Us  = sm + 4736;
    float* Gs  = sm;
    float* VPs = sm + 9344;
    float* Os  = sm + 14720;
    float* gus = sm + 14720;
    float* bus = sm + 14976;
    float* smG = sm + 15800;
    float* smB = sm + 15816;

    int blk = blockIdx.x;
    int b   = blk >> 7;
    int hw0 = (blk & 127) * 8;
    int tid  = threadIdx.x;
    int lane = tid & 31;
    int px   = tid >> 5;
    int g = lane >> 2, tq = lane & 3;
    const size_t pixbase = (size_t)b * C_ * T_ * HW_ + hw0;
    const float*  xg = x      + pixbase;
    const __half* ug = d_u16  + pixbase;
    const __half* vg = d_vp16 + pixbase;

    int s_ = tid >> 3, px_ = tid & 7;
    float gu = 0.f, bu = 0.f;

    float acc1[2][4][4];
    #pragma unroll
    for (int i = 0; i < 2; i++)
        #pragma unroll
        for (int j = 0; j < 4; j++)
            #pragma unroll
            for (int r = 0; r < 4; r++) acc1[i][j][r] = 0.f;

    float4 ph[4];
    uint4  pu4[2];
    auto prefetch1 = [&](int c0) {
        #pragma unroll
        for (int r = 0; r < 4; r++) {
            int flat = r * 256 + tid;            // x float4 units
            int pp = flat & 1;
            int t  = (flat >> 1) & 31;
            int c  = flat >> 6;
            ph[r] = *reinterpret_cast<const float4*>(
                xg + ((size_t)(c0 + c) * 32 + t) * 1024 + pp * 4);
        }
        #pragma unroll
        for (int r = 0; r < 2; r++) {
            int flat = r * 256 + tid;            // u half8 units
            int c = flat >> 5, t = flat & 31;
            pu4[r] = *reinterpret_cast<const uint4*>(
                ug + ((size_t)(c0 + c) * 32 + t) * 1024);
        }
    };
    auto store1 = [&](int c0) {
        #pragma unroll
        for (int r = 0; r < 4; r++) {
            int flat = r * 256 + tid;
            int pp = flat & 1;
            int t  = (flat >> 1) & 31;
            int c  = flat >> 6;
            float gam = gamma[c0 + c];
            int so = c * HS_CSTR + t * 9 + pp * 4;
            Hs[so] = gam*ph[r].x; Hs[so+1] = gam*ph[r].y;
            Hs[so+2] = gam*ph[r].z; Hs[so+3] = gam*ph[r].w;
        }
        #pragma unroll
        for (int r = 0; r < 2; r++) {
            int flat = r * 256 + tid;
            int c = flat >> 5, t = flat & 31;
            int so = c * HS_CSTR + t * 9;
            const __half2* hp = reinterpret_cast<const __half2*>(&pu4[r]);
            #pragma unroll
            for (int j = 0; j < 4; j++) {
                float2 f = __half22float2(hp[j]);
                Us[so + j*2]     = f.x;
                Us[so + j*2 + 1] = f.y;
            }
        }
    };

    prefetch1(0);
    for (int c0 = 0; c0 < 512; c0 += 16) {
        store1(c0);
        if (tid < 16)       smG[tid]      = gamma[c0 + tid];
        else if (tid < 32)  smB[tid - 16] = beta[c0 + tid - 16];
        __syncthreads();
        if (c0 + 16 < 512) prefetch1(c0 + 16);

        const uint32_t* Hu = reinterpret_cast<const uint32_t*>(Hs);
        const uint32_t* Uu = reinterpret_cast<const uint32_t*>(Us);
        #pragma unroll
        for (int kk = 0; kk < 16; kk += 8) {
            uint32_t a[2][4], bq[4][2];
            #pragma unroll
            for (int mf = 0; mf < 2; mf++) {
                int base = (kk + tq) * HS_CSTR + (mf * 16 + g) * 9 + px;
                a[mf][0] = Hu[base];
                a[mf][1] = Hu[base + 72];
                a[mf][2] = Hu[base + 4 * HS_CSTR];
                a[mf][3] = Hu[base + 4 * HS_CSTR + 72];
            }
            #pragma unroll
            for (int nf = 0; nf < 4; nf++) {
                int base = (kk + tq) * HS_CSTR + (nf * 8 + g) * 9 + px;
                bq[nf][0] = Uu[base];
                bq[nf][1] = Uu[base + 4 * HS_CSTR];
            }
            #pragma unroll
            for (int mf = 0; mf < 2; mf++)
                #pragma unroll
                for (int nf = 0; nf < 4; nf++)
                    MMA_TF32(acc1[mf][nf][0], acc1[mf][nf][1], acc1[mf][nf][2], acc1[mf][nf][3],
                             a[mf][0], a[mf][1], a[mf][2], a[mf][3],
                             bq[nf][0], bq[nf][1]);
        }
        #pragma unroll
        for (int c = 0; c < 16; c++) {
            float uv = Us[c * HS_CSTR + s_ * 9 + px_];
            gu += smG[c] * uv;
            bu += smB[c] * uv;
        }
        __syncthreads();
    }

    gus[s_ * 8 + px_] = gu;
    bus[s_ * 8 + px_] = bu;
    __syncthreads();

    const float scale = 0.044194173824159216f;
    #pragma unroll
    for (int mf = 0; mf < 2; mf++) {
        int t0 = mf * 16 + g, t1 = t0 + 8;
        float r0 = d_rstd[b*32 + t0], m0v = d_mean[b*32 + t0];
        float r1 = d_rstd[b*32 + t1], m1v = d_mean[b*32 + t1];
        #pragma unroll
        for (int nf = 0; nf < 4; nf++) {
            int s0 = nf * 8 + tq * 2, s1 = s0 + 1;
            float gu0 = gus[s0*8 + px], bu0 = bus[s0*8 + px];
            float gu1 = gus[s1*8 + px], bu1 = bus[s1*8 + px];
            Gs[t0 * GS_TSTR + s0 * 9 + px] = (r0*(acc1[mf][nf][0] - m0v*gu0) + bu0) * scale;
            Gs[t0 * GS_TSTR + s1 * 9 + px] = (r0*(acc1[mf][nf][1] - m0v*gu1) + bu1) * scale;
            Gs[t1 * GS_TSTR + s0 * 9 + px] = (r1*(acc1[mf][nf][2] - m1v*gu0) + bu0) * scale;
            Gs[t1 * GS_TSTR + s1 * 9 + px] = (r1*(acc1[mf][nf][3] - m1v*gu1) + bu1) * scale;
        }
    }
    __syncthreads();

    {
        int pxs = tid & 7;
        int t   = tid >> 3;
        int gb  = t * GS_TSTR + pxs;
        float mx = -1e30f;
        for (int s = 0; s <= t; s++) mx = fmaxf(mx, Gs[gb + s * 9]);
        float Z = 0.f;
        for (int s = 0; s <= t; s++) Z += __expf(Gs[gb + s * 9] - mx);
        float iz = 1.f / Z;
        for (int s = 0; s < 32; s++) {
            float v = (s <= t) ? __expf(Gs[gb + s * 9] - mx) * iz : 0.f;
            Gs[gb + s * 9] = tf32r(v);
        }
    }
    __syncthreads();

    // ---------------- phase 4: out = G @ vp^T + x ----------------
    const uint32_t* Gu = reinterpret_cast<const uint32_t*>(Gs);
    uint4 pv4[2];
    auto prefetch_v = [&](int oc) {
        #pragma unroll
        for (int r = 0; r < 2; r++) {
            int flat = r * 256 + tid;            // vp half8 units
            int s = flat >> 4, o = flat & 15;
            pv4[r] = *reinterpret_cast<const uint4*>(
                vg + ((size_t)(oc + o) * 32 + s) * 1024);
        }
    };

    prefetch_v(0);
    for (int oc = 0; oc < 512; oc += 16) {
        #pragma unroll
        for (int r = 0; r < 2; r++) {
            int flat = r * 256 + tid;
            int s = flat >> 4, o = flat & 15;
            int so = s * VP_SSTR + o * 9;
            const __half2* hp = reinterpret_cast<const __half2*>(&pv4[r]);
            #pragma unroll
            for (int j = 0; j < 4; j++) {
                float2 f = __half22float2(hp[j]);
                VPs[so + j*2]     = f.x;
                VPs[so + j*2 + 1] = f.y;
            }
        }
        __syncthreads();
        if (oc + 16 < 512) prefetch_v(oc + 16);

        // hoist residual x loads for THIS chunk (overlap with MMA below)
        float4 pxv[4];
        #pragma unroll
        for (int r = 0; r < 4; r++) {
            int flat = r * 256 + tid;
            int pp = flat & 1;
            int t  = (flat >> 1) & 31;
            int o  = flat >> 6;
            pxv[r] = *reinterpret_cast<const float4*>(
                xg + ((size_t)(oc + o) * 32 + t) * 1024 + pp * 4);
        }

        float acc2[2][2][4];
        #pragma unroll
        for (int i = 0; i < 2; i++)
            #pragma unroll
            for (int j = 0; j < 2; j++)
                #pragma unroll
                for (int r = 0; r < 4; r++) acc2[i][j][r] = 0.f;

        const uint32_t* Vu = reinterpret_cast<const uint32_t*>(VPs);
        #pragma unroll
        for (int kk = 0; kk < 32; kk += 8) {
            uint32_t a[2][4], bq[2][2];
            #pragma unroll
            for (int mf = 0; mf < 2; mf++) {
                int base = (mf * 16 + g) * GS_TSTR + (kk + tq) * 9 + px;
                a[mf][0] = Gu[base];
                a[mf][1] = Gu[base + 8 * GS_TSTR];
                a[mf][2] = Gu[base + 36];
                a[mf][3] = Gu[base + 8 * GS_TSTR + 36];
            }
            #pragma unroll
            for (int nf = 0; nf < 2; nf++) {
                int base = (kk + tq) * VP_SSTR + (nf * 8 + g) * 9 + px;
                bq[nf][0] = Vu[base];
                bq[nf][1] = Vu[base + 4 * VP_SSTR];
            }
            #pragma unroll
            for (int mf = 0; mf < 2; mf++)
                #pragma unroll
                for (int nf = 0; nf < 2; nf++)
                    MMA_TF32(acc2[mf][nf][0], acc2[mf][nf][1], acc2[mf][nf][2], acc2[mf][nf][3],
                             a[mf][0], a[mf][1], a[mf][2], a[mf][3],
                             bq[nf][0], bq[nf][1]);
        }

        #pragma unroll
        for (int mf = 0; mf < 2; mf++) {
            #pragma unroll
            for (int nf = 0; nf < 2; nf++) {
                int t = mf * 16 + g;
                int o = nf * 8 + tq * 2;
                Os[t * OS_TSTR + o * 10 + px]             = acc2[mf][nf][0];
                Os[t * OS_TSTR + (o + 1) * 10 + px]       = acc2[mf][nf][1];
                Os[(t + 8) * OS_TSTR + o * 10 + px]       = acc2[mf][nf][2];
                Os[(t + 8) * OS_TSTR + (o + 1) * 10 + px] = acc2[mf][nf][3];
            }
        }
        __syncthreads();

        #pragma unroll
        for (int r = 0; r < 4; r++) {
            int flat = r * 256 + tid;
            int pp = flat & 1;
            int t  = (flat >> 1) & 31;
            int o  = flat >> 6;
            size_t gg = pixbase + ((size_t)(oc + o) * 32 + t) * 1024 + pp * 4;
            int so = t * OS_TSTR + o * 10 + pp * 4;
            float4 ov;
            ov.x = Os[so]     + pxv[r].x;
            ov.y = Os[so + 1] + pxv[r].y;
            ov.z = Os[so + 2] + pxv[r].z;
            ov.w = Os[so + 3] + pxv[r].w;
            *reinterpret_cast<float4*>(out + gg) = ov;
        }
        __syncthreads();
    }
}

// ---------------------------------------------------------------------------
extern "C" void kernel_launch(void* const* d_in, const int* in_sizes, int n_in,
                              void* d_out, int out_size)
{
    const float* x     = (const float*)d_in[0];
    const float* gamma = (const float*)d_in[1];
    const float* beta  = (const float*)d_in[2];
    const float* wq    = (const float*)d_in[3];
    const float* wk    = (const float*)d_in[4];
    const float* wv    = (const float*)d_in[5];
    const float* wproj = (const float*)d_in[6];
    float* out = (float*)d_out;

    cudaFuncSetAttribute(gemm_uv_f16, cudaFuncAttributeMaxDynamicSharedMemorySize,
                         GEMM_SMEM);
    cudaFuncSetAttribute(attn_mma, cudaFuncAttributeMaxDynamicSharedMemorySize,
                         ATTN_SMEM_FLOATS * 4);

    prep_w2<<<1024, 256>>>(wq, wk, wv, wproj, gamma, beta);
    conv_x16<<<dim3(512, 8, B_), 256>>>(x);
    reduce_stats<<<128, 128>>>();
    gemm_uv_f16<<<dim3(8, 256, B_), 128, GEMM_SMEM>>>();
    attn_mma<<<512, 256, ATTN_SMEM_FLOATS * 4>>>(x, gamma, beta, out);
}

// round 10
// speedup vs baseline: 3.2310x; 1.0293x over previous
#include <cuda_runtime.h>
#include <cuda_fp16.h>
#include <math.h>
#include <stdint.h>

#define B_   4
#define C_   512
#define T_   32
#define HW_  1024
#define NCOL (T_*HW_)            // 32768 columns per batch
#define TOT  (B_*C_*T_*HW_)

// Scratch
__device__ __half d_x16[TOT];      // x transposed+fp16: [b][n][c] (n = t*1024+hw)
__device__ __half d_W16[1024*512]; // W2G = W2·diag(gamma), [m][k], fp16
__device__ __half d_u16[TOT];      // u  (fp16, [b][c][n])
__device__ __half d_vp16[TOT];     // v' (fp16, [b][c][n])
__device__ float  d_w2g1[1024];    // row sums of W16
__device__ float  d_w2b[1024];     // W2·beta
__device__ float  d_psum[16384];   // per-block partial sums (conv_x16)
__device__ float  d_psum2[16384];
__device__ float  d_mean[B_*T_];
__device__ float  d_rstd[B_*T_];

__device__ __forceinline__ float tf32r(float x) {
    uint32_t r;
    asm("cvt.rna.tf32.f32 %0, %1;" : "=r"(r) : "f"(x));
    return __uint_as_float(r);
}

__device__ __forceinline__ void cp16g(void* dst, const void* src) {
    unsigned d = (unsigned)__cvta_generic_to_shared(dst);
    asm volatile("cp.async.cg.shared.global [%0], [%1], 16;\n" :: "r"(d), "l"(src));
}

#define MMA_F16(d0,d1,d2,d3,a0,a1,a2,a3,b0,b1) \
    asm volatile("mma.sync.aligned.m16n8k16.row.col.f32.f16.f16.f32 " \
                 "{%0,%1,%2,%3},{%4,%5,%6,%7},{%8,%9},{%0,%1,%2,%3};" \
                 : "+f"(d0), "+f"(d1), "+f"(d2), "+f"(d3) \
                 : "r"(a0), "r"(a1), "r"(a2), "r"(a3), "r"(b0), "r"(b1))

#define MMA_TF32(d0,d1,d2,d3,a0,a1,a2,a3,b0,b1) \
    asm volatile("mma.sync.aligned.m16n8k8.row.col.f32.tf32.tf32.f32 " \
                 "{%0,%1,%2,%3},{%4,%5,%6,%7},{%8,%9},{%0,%1,%2,%3};" \
                 : "+f"(d0), "+f"(d1), "+f"(d2), "+f"(d3) \
                 : "r"(a0), "r"(a1), "r"(a2), "r"(a3), "r"(b0), "r"(b1))

// ---------------------------------------------------------------------------
// prep_w2: one block per m. W16[m][k]=fp16(raw[m][k]*gamma[k]);
//          w2g1[m]=sum_k W16; w2b[m]=raw·beta
// ---------------------------------------------------------------------------
__global__ void prep_w2(const float* __restrict__ wq, const float* __restrict__ wk,
                        const float* __restrict__ wv, const float* __restrict__ wproj,
                        const float* __restrict__ gamma, const float* __restrict__ beta)
{
    int m = blockIdx.x;
    int tid = threadIdx.x;
    float lg = 0.f, lb = 0.f;
    #pragma unroll
    for (int jj = 0; jj < 2; jj++) {
        int j = jj * 256 + tid;
        float acc = 0.f;
        if (m < 512) {
            #pragma unroll 4
            for (int o = 0; o < 512; o++)
                acc += wq[o*512 + m] * wk[o*512 + j];
        } else {
            int i = m - 512;
            #pragma unroll 4
            for (int c = 0; c < 512; c++)
                acc += wproj[i*512 + c] * wv[c*512 + j];
        }
        __half wh = __float2half(acc * gamma[j]);
        d_W16[(size_t)m * 512 + j] = wh;
        lg += __half2float(wh);
        lb += acc * beta[j];
    }
    __shared__ float red[16];
    #pragma unroll
    for (int o = 16; o > 0; o >>= 1) {
        lg += __shfl_down_sync(0xffffffffu, lg, o);
        lb += __shfl_down_sync(0xffffffffu, lb, o);
    }
    int w = tid >> 5;
    if ((tid & 31) == 0) { red[w] = lg; red[8 + w] = lb; }
    __syncthreads();
    if (tid == 0) {
        float G = 0.f, Bv = 0.f;
        for (int k = 0; k < 8; k++) { G += red[k]; Bv += red[8 + k]; }
        d_w2g1[m] = G;
        d_w2b[m]  = Bv;
    }
}

// ---------------------------------------------------------------------------
// conv_x16: x [b][c][n] fp32 -> d_x16 [b][n][c] fp16, 64c x 64n smem tiles,
// PLUS per-block LN partial sums (each block covers a single (b,t)).
// ---------------------------------------------------------------------------
__global__ void conv_x16(const float* __restrict__ x)
{
    __shared__ float sT[64][65];
    __shared__ float rsum[8], rsum2[8];
    int b   = blockIdx.z;
    int c0  = blockIdx.y * 64;
    int n0t = blockIdx.x * 64;
    int tid = threadIdx.x;
    const float* xb = x + (size_t)b * C_ * NCOL;
    float s = 0.f, ss = 0.f;
    #pragma unroll
    for (int r = 0; r < 4; r++) {
        int flat = r * 256 + tid;           // 0..1023 float4 units
        int cr = flat >> 4, nq = flat & 15;
        float4 v = *reinterpret_cast<const float4*>(
            xb + (size_t)(c0 + cr) * NCOL + n0t + nq * 4);
        sT[cr][nq*4+0] = v.x; sT[cr][nq*4+1] = v.y;
        sT[cr][nq*4+2] = v.z; sT[cr][nq*4+3] = v.w;
        s  += v.x + v.y + v.z + v.w;
        ss += v.x*v.x + v.y*v.y + v.z*v.z + v.w*v.w;
    }
    #pragma unroll
    for (int o = 16; o > 0; o >>= 1) {
        s  += __shfl_down_sync(0xffffffffu, s,  o);
        ss += __shfl_down_sync(0xffffffffu, ss, o);
    }
    if ((tid & 31) == 0) { rsum[tid >> 5] = s; rsum2[tid >> 5] = ss; }
    __syncthreads();
    if (tid == 0) {
        float S = 0.f, SS = 0.f;
        #pragma unroll
        for (int k = 0; k < 8; k++) { S += rsum[k]; SS += rsum2[k]; }
        int t = blockIdx.x >> 4, nIn = blockIdx.x & 15;
        int pid = ((b * 32 + t) * 8 + blockIdx.y) * 16 + nIn;
        d_psum[pid]  = S;
        d_psum2[pid] = SS;
    }
    int nr = tid >> 2, cq = tid & 3;        // 64 n-rows x 4 chunks of 16c
    uint32_t pk[8];
    #pragma unroll
    for (int j = 0; j < 8; j++) {
        __half2 h2 = __floats2half2_rn(sT[cq*16 + j*2][nr], sT[cq*16 + j*2 + 1][nr]);
        pk[j] = *reinterpret_cast<uint32_t*>(&h2);
    }
    __half* dst = d_x16 + ((size_t)b * NCOL + n0t + nr) * 512 + c0 + cq * 16;
    *reinterpret_cast<uint4*>(dst)     = make_uint4(pk[0], pk[1], pk[2], pk[3]);
    *reinterpret_cast<uint4*>(dst + 8) = make_uint4(pk[4], pk[5], pk[6], pk[7]);
}

// ---------------------------------------------------------------------------
// reduce_stats: 128 blocks (one per (b,t)), sum 128 partials -> mean/rstd
// ---------------------------------------------------------------------------
__global__ void reduce_stats()
{
    int g = blockIdx.x;
    int tid = threadIdx.x;                  // 128 threads
    float s  = d_psum[g * 128 + tid];
    float ss = d_psum2[g * 128 + tid];
    #pragma unroll
    for (int o = 16; o > 0; o >>= 1) {
        s  += __shfl_down_sync(0xffffffffu, s,  o);
        ss += __shfl_down_sync(0xffffffffu, ss, o);
    }
    __shared__ float sm[8];
    if ((tid & 31) == 0) { sm[tid >> 5] = s; sm[4 + (tid >> 5)] = ss; }
    __syncthreads();
    if (tid == 0) {
        float S = sm[0] + sm[1] + sm[2] + sm[3];
        float SS = sm[4] + sm[5] + sm[6] + sm[7];
        float invn = 1.f / (float)(C_ * HW_);
        float m = S * invn;
        float var = SS * invn - m * m;
        d_mean[g] = m;
        d_rstd[g] = rsqrtf(var + 1e-6f);
    }
}

// ---------------------------------------------------------------------------
// fp16 GEMM: y = W16·x16^T per batch; epilogue u/vp = fp16(rstd·y + bias).
// Block 128x128, 4 warps (2x2), warp tile 64x64. 4-stage cp.async, k=32/stage.
// ---------------------------------------------------------------------------
#define AROW 40                  // halfs per k-row (32 + 8 pad)
#define STH  (128*AROW)          // 5120 halfs per A or B stage tile
#define STAGEH (2*STH)           // 10240 halfs per stage
#define GEMM_SMEM (4*STAGEH*2)   // bytes = 81920

__global__ __launch_bounds__(128, 2) void gemm_uv_f16()
{
    extern __shared__ __half smh[];
    int b  = blockIdx.z;
    int m0 = blockIdx.x * 128;
    int n0 = blockIdx.y * 128;
    const __half* xb = d_x16 + (size_t)b * NCOL * 512;
    int tid  = threadIdx.x;
    int lane = tid & 31;
    int w    = tid >> 5;
    int warpM = w >> 1, warpN = w & 1;
    int g = lane >> 2, tq = lane & 3;
    int am = warpM * 64 + g;
    int bn = warpN * 64 + g;

    float acc[4][8][4];
    #pragma unroll
    for (int i = 0; i < 4; i++)
        #pragma unroll
        for (int j = 0; j < 8; j++)
            #pragma unroll
            for (int r = 0; r < 4; r++) acc[i][j][r] = 0.f;

    auto load_stage = [&](int k0, int buf) {
        __half* As = smh + buf * STAGEH;
        __half* Bs = As + STH;
        #pragma unroll
        for (int r = 0; r < 4; r++) {
            int ch = r * 128 + tid;          // 0..511
            int row = ch >> 2;
            int q   = ch & 3;
            cp16g(As + row * AROW + q * 8, &d_W16[(size_t)(m0 + row) * 512 + k0 + q * 8]);
            cp16g(Bs + row * AROW + q * 8, &xb[(size_t)(n0 + row) * 512 + k0 + q * 8]);
        }
    };

    #pragma unroll
    for (int p = 0; p < 3; p++) {
        load_stage(p * 32, p);
        asm volatile("cp.async.commit_group;\n");
    }

    for (int it = 0; it < 16; it++) {
        asm volatile("cp.async.wait_group 2;\n");
        __syncthreads();

        const uint32_t* Asw = reinterpret_cast<const uint32_t*>(smh + (it & 3) * STAGEH);
        const uint32_t* Bsw = Asw + STH / 2;

        #pragma unroll
        for (int ks = 0; ks < 16; ks += 8) {
            uint32_t a[4][4], bq[8][2];
            #pragma unroll
            for (int mf = 0; mf < 4; mf++) {
                int r0 = (am + mf * 16) * 20 + ks + tq;
                int r1 = (am + mf * 16 + 8) * 20 + ks + tq;
                a[mf][0] = Asw[r0];
                a[mf][1] = Asw[r1];
                a[mf][2] = Asw[r0 + 4];
                a[mf][3] = Asw[r1 + 4];
            }
            #pragma unroll
            for (int nf = 0; nf < 8; nf++) {
                int rb = (bn + nf * 8) * 20 + ks + tq;
                bq[nf][0] = Bsw[rb];
                bq[nf][1] = Bsw[rb + 4];
            }
            #pragma unroll
            for (int mf = 0; mf < 4; mf++)
                #pragma unroll
                for (int nf = 0; nf < 8; nf++)
                    MMA_F16(acc[mf][nf][0], acc[mf][nf][1], acc[mf][nf][2], acc[mf][nf][3],
                            a[mf][0], a[mf][1], a[mf][2], a[mf][3],
                            bq[nf][0], bq[nf][1]);
        }
        if (it + 3 < 16)
            load_stage((it + 3) * 32, (it + 3) & 3);
        asm volatile("cp.async.commit_group;\n");
    }

    // epilogue: LN correction, fp16 outputs
    int tcol = blockIdx.y >> 3;
    int gidx = b * 32 + tcol;
    float rstdv = d_rstd[gidx];
    float rm    = rstdv * d_mean[gidx];
    bool isU = (m0 < 512);
    __half* outb = isU ? (d_u16  + (size_t)(b * 512 + m0)       * NCOL)
                       : (d_vp16 + (size_t)(b * 512 + m0 - 512) * NCOL);
    #pragma unroll
    for (int mf = 0; mf < 4; mf++) {
        int mrow = warpM * 64 + mf * 16 + g;
        int mg0 = m0 + mrow, mg1 = m0 + mrow + 8;
        float bias0 = d_w2b[mg0] - rm * d_w2g1[mg0];
        float bias1 = d_w2b[mg1] - rm * d_w2g1[mg1];
        #pragma unroll
        for (int nf = 0; nf < 8; nf++) {
            int ncol = n0 + warpN * 64 + nf * 8 + tq * 2;
            __half2 lo = __floats2half2_rn(rstdv * acc[mf][nf][0] + bias0,
                                           rstdv * acc[mf][nf][1] + bias0);
            __half2 hi = __floats2half2_rn(rstdv * acc[mf][nf][2] + bias1,
                                           rstdv * acc[mf][nf][3] + bias1);
            *reinterpret_cast<__half2*>(outb + (size_t)mrow * NCOL + ncol)       = lo;
            *reinterpret_cast<__half2*>(outb + (size_t)(mrow + 8) * NCOL + ncol) = hi;
        }
    }
}

// ---------------------------------------------------------------------------
// Tensor-core attention + residual, LN folded.
// Phase 1 now reads x from d_x16 (fp16, [n][c]) instead of fp32 x:
// halves phase-1 x DRAM traffic and global load instruction count.
// Residual (phase 4) keeps exact fp32 x.
// ---------------------------------------------------------------------------
#define HS_CSTR 296
#define GS_TSTR 292
#define VP_SSTR 168
#define OS_TSTR 164
#define ATTN_SMEM_FLOATS (9344 + 5376 + 5248)   // 19968 floats

__global__ __launch_bounds__(256, 2) void attn_mma(const float* __restrict__ x,
                                                   const float* __restrict__ gamma,
                                                   const float* __restrict__ beta,
                                                   float* __restrict__ out)
{
    extern __shared__ float sm[];
    float* Hs  = sm;
    float* Us  = sm + 4736;
    float* Gs  = sm;
    float* VPs = sm + 9344;
    float* Os  = sm + 14720;
    float* gus = sm + 14720;
    float* bus = sm + 14976;
    float* smG = sm + 15800;
    float* smB = sm + 15816;

    int blk = blockIdx.x;
    int b   = blk >> 7;
    int hw0 = (blk & 127) * 8;
    int tid  = threadIdx.x;
    int lane = tid & 31;
    int px   = tid >> 5;
    int g = lane >> 2, tq = lane & 3;
    const size_t pixbase = (size_t)b * C_ * T_ * HW_ + hw0;
    const float*  xg = x      + pixbase;                 // fp32 (residual only)
    const __half* xh = d_x16  + (size_t)b * NCOL * 512;  // fp16 [n][c]
    const __half* ug = d_u16  + pixbase;
    const __half* vg = d_vp16 + pixbase;

    int s_ = tid >> 3, px_ = tid & 7;
    float gu = 0.f, bu = 0.f;

    float acc1[2][4][4];
    #pragma unroll
    for (int i = 0; i < 2; i++)
        #pragma unroll
        for (int j = 0; j < 4; j++)
            #pragma unroll
            for (int r = 0; r < 4; r++) acc1[i][j][r] = 0.f;

    uint4 pxh[2], pu4[2];
    auto prefetch1 = [&](int c0) {
        #pragma unroll
        for (int r = 0; r < 2; r++) {
            int flat = r * 256 + tid;            // 0..511: q2 x px8 x t32
            int q   = flat & 1;
            int pxl = (flat >> 1) & 7;
            int t   = flat >> 4;
            pxh[r] = *reinterpret_cast<const uint4*>(
                xh + ((size_t)t * 1024 + hw0 + pxl) * 512 + c0 + q * 8);
        }
        #pragma unroll
        for (int r = 0; r < 2; r++) {
            int flat = r * 256 + tid;            // u half8 units: c16 x t32
            int c = flat >> 5, t = flat & 31;
            pu4[r] = *reinterpret_cast<const uint4*>(
                ug + ((size_t)(c0 + c) * 32 + t) * 1024);
        }
    };
    auto store1 = [&](int c0) {
        #pragma unroll
        for (int r = 0; r < 2; r++) {
            int flat = r * 256 + tid;
            int q   = flat & 1;
            int pxl = (flat >> 1) & 7;
            int t   = flat >> 4;
            const __half2* hp = reinterpret_cast<const __half2*>(&pxh[r]);
            #pragma unroll
            for (int j = 0; j < 4; j++) {
                float2 f = __half22float2(hp[j]);
                int c = q * 8 + j * 2;
                Hs[(c)     * HS_CSTR + t * 9 + pxl] = gamma[c0 + c]     * f.x;
                Hs[(c + 1) * HS_CSTR + t * 9 + pxl] = gamma[c0 + c + 1] * f.y;
            }
        }
        #pragma unroll
        for (int r = 0; r < 2; r++) {
            int flat = r * 256 + tid;
            int c = flat >> 5, t = flat & 31;
            int so = c * HS_CSTR + t * 9;
            const __half2* hp = reinterpret_cast<const __half2*>(&pu4[r]);
            #pragma unroll
            for (int j = 0; j < 4; j++) {
                float2 f = __half22float2(hp[j]);
                Us[so + j*2]     = f.x;
                Us[so + j*2 + 1] = f.y;
            }
        }
    };

    prefetch1(0);
    for (int c0 = 0; c0 < 512; c0 += 16) {
        store1(c0);
        if (tid < 16)       smG[tid]      = gamma[c0 + tid];
        else if (tid < 32)  smB[tid - 16] = beta[c0 + tid - 16];
        __syncthreads();
        if (c0 + 16 < 512) prefetch1(c0 + 16);

        const uint32_t* Hu = reinterpret_cast<const uint32_t*>(Hs);
        const uint32_t* Uu = reinterpret_cast<const uint32_t*>(Us);
        #pragma unroll
        for (int kk = 0; kk < 16; kk += 8) {
            uint32_t a[2][4], bq[4][2];
            #pragma unroll
            for (int mf = 0; mf < 2; mf++) {
                int base = (kk + tq) * HS_CSTR + (mf * 16 + g) * 9 + px;
                a[mf][0] = Hu[base];
                a[mf][1] = Hu[base + 72];
                a[mf][2] = Hu[base + 4 * HS_CSTR];
                a[mf][3] = Hu[base + 4 * HS_CSTR + 72];
            }
            #pragma unroll
            for (int nf = 0; nf < 4; nf++) {
                int base = (kk + tq) * HS_CSTR + (nf * 8 + g) * 9 + px;
                bq[nf][0] = Uu[base];
                bq[nf][1] = Uu[base + 4 * HS_CSTR];
            }
            #pragma unroll
            for (int mf = 0; mf < 2; mf++)
                #pragma unroll
                for (int nf = 0; nf < 4; nf++)
                    MMA_TF32(acc1[mf][nf][0], acc1[mf][nf][1], acc1[mf][nf][2], acc1[mf][nf][3],
                             a[mf][0], a[mf][1], a[mf][2], a[mf][3],
                             bq[nf][0], bq[nf][1]);
        }
        #pragma unroll
        for (int c = 0; c < 16; c++) {
            float uv = Us[c * HS_CSTR + s_ * 9 + px_];
            gu += smG[c] * uv;
            bu += smB[c] * uv;
        }
        __syncthreads();
    }

    gus[s_ * 8 + px_] = gu;
    bus[s_ * 8 + px_] = bu;
    __syncthreads();

    const float scale = 0.044194173824159216f;
    #pragma unroll
    for (int mf = 0; mf < 2; mf++) {
        int t0 = mf * 16 + g, t1 = t0 + 8;
        float r0 = d_rstd[b*32 + t0], m0v = d_mean[b*32 + t0];
        float r1 = d_rstd[b*32 + t1], m1v = d_mean[b*32 + t1];
        #pragma unroll
        for (int nf = 0; nf < 4; nf++) {
            int s0 = nf * 8 + tq * 2, s1 = s0 + 1;
            float gu0 = gus[s0*8 + px], bu0 = bus[s0*8 + px];
            float gu1 = gus[s1*8 + px], bu1 = bus[s1*8 + px];
            Gs[t0 * GS_TSTR + s0 * 9 + px] = (r0*(acc1[mf][nf][0] - m0v*gu0) + bu0) * scale;
            Gs[t0 * GS_TSTR + s1 * 9 + px] = (r0*(acc1[mf][nf][1] - m0v*gu1) + bu1) * scale;
            Gs[t1 * GS_TSTR + s0 * 9 + px] = (r1*(acc1[mf][nf][2] - m1v*gu0) + bu0) * scale;
            Gs[t1 * GS_TSTR + s1 * 9 + px] = (r1*(acc1[mf][nf][3] - m1v*gu1) + bu1) * scale;
        }
    }
    __syncthreads();

    {
        int pxs = tid & 7;
        int t   = tid >> 3;
        int gb  = t * GS_TSTR + pxs;
        float mx = -1e30f;
        for (int s = 0; s <= t; s++) mx = fmaxf(mx, Gs[gb + s * 9]);
        float Z = 0.f;
        for (int s = 0; s <= t; s++) Z += __expf(Gs[gb + s * 9] - mx);
        float iz = 1.f / Z;
        for (int s = 0; s < 32; s++) {
            float v = (s <= t) ? __expf(Gs[gb + s * 9] - mx) * iz : 0.f;
            Gs[gb + s * 9] = tf32r(v);
        }
    }
    __syncthreads();

    // ---------------- phase 4: out = G @ vp^T + x ----------------
    const uint32_t* Gu = reinterpret_cast<const uint32_t*>(Gs);
    uint4 pv4[2];
    auto prefetch_v = [&](int oc) {
        #pragma unroll
        for (int r = 0; r < 2; r++) {
            int flat = r * 256 + tid;            // vp half8 units
            int s = flat >> 4, o = flat & 15;
            pv4[r] = *reinterpret_cast<const uint4*>(
                vg + ((size_t)(oc + o) * 32 + s) * 1024);
        }
    };

    prefetch_v(0);
    for (int oc = 0; oc < 512; oc += 16) {
        #pragma unroll
        for (int r = 0; r < 2; r++) {
            int flat = r * 256 + tid;
            int s = flat >> 4, o = flat & 15;
            int so = s * VP_SSTR + o * 9;
            const __half2* hp = reinterpret_cast<const __half2*>(&pv4[r]);
            #pragma unroll
            for (int j = 0; j < 4; j++) {
                float2 f = __half22float2(hp[j]);
                VPs[so + j*2]     = f.x;
                VPs[so + j*2 + 1] = f.y;
            }
        }
        __syncthreads();
        if (oc + 16 < 512) prefetch_v(oc + 16);

        // hoist residual x loads for THIS chunk (overlap with MMA below)
        float4 pxv[4];
        #pragma unroll
        for (int r = 0; r < 4; r++) {
            int flat = r * 256 + tid;
            int pp = flat & 1;
            int t  = (flat >> 1) & 31;
            int o  = flat >> 6;
            pxv[r] = *reinterpret_cast<const float4*>(
                xg + ((size_t)(oc + o) * 32 + t) * 1024 + pp * 4);
        }

        float acc2[2][2][4];
        #pragma unroll
        for (int i = 0; i < 2; i++)
            #pragma unroll
            for (int j = 0; j < 2; j++)
                #pragma unroll
                for (int r = 0; r < 4; r++) acc2[i][j][r] = 0.f;

        const uint32_t* Vu = reinterpret_cast<const uint32_t*>(VPs);
        #pragma unroll
        for (int kk = 0; kk < 32; kk += 8) {
            uint32_t a[2][4], bq[2][2];
            #pragma unroll
            for (int mf = 0; mf < 2; mf++) {
                int base = (mf * 16 + g) * GS_TSTR + (kk + tq) * 9 + px;
                a[mf][0] = Gu[base];
                a[mf][1] = Gu[base + 8 * GS_TSTR];
                a[mf][2] = Gu[base + 36];
                a[mf][3] = Gu[base + 8 * GS_TSTR + 36];
            }
            #pragma unroll
            for (int nf = 0; nf < 2; nf++) {
                int base = (kk + tq) * VP_SSTR + (nf * 8 + g) * 9 + px;
                bq[nf][0] = Vu[base];
                bq[nf][1] = Vu[base + 4 * VP_SSTR];
            }
            #pragma unroll
            for (int mf = 0; mf < 2; mf++)
                #pragma unroll
                for (int nf = 0; nf < 2; nf++)
                    MMA_TF32(acc2[mf][nf][0], acc2[mf][nf][1], acc2[mf][nf][2], acc2[mf][nf][3],
                             a[mf][0], a[mf][1], a[mf][2], a[mf][3],
                             bq[nf][0], bq[nf][1]);
        }

        #pragma unroll
        for (int mf = 0; mf < 2; mf++) {
            #pragma unroll
            for (int nf = 0; nf < 2; nf++) {
                int t = mf * 16 + g;
                int o = nf * 8 + tq * 2;
                Os[t * OS_TSTR + o * 10 + px]             = acc2[mf][nf][0];
                Os[t * OS_TSTR + (o + 1) * 10 + px]       = acc2[mf][nf][1];
                Os[(t + 8) * OS_TSTR + o * 10 + px]       = acc2[mf][nf][2];
                Os[(t + 8) * OS_TSTR + (o + 1) * 10 + px] = acc2[mf][nf][3];
            }
        }
        __syncthreads();

        #pragma unroll
        for (int r = 0; r < 4; r++) {
            int flat = r * 256 + tid;
            int pp = flat & 1;
            int t  = (flat >> 1) & 31;
            int o  = flat >> 6;
            size_t gg = pixbase + ((size_t)(oc + o) * 32 + t) * 1024 + pp * 4;
            int so = t * OS_TSTR + o * 10 + pp * 4;
            float4 ov;
            ov.x = Os[so]     + pxv[r].x;
            ov.y = Os[so + 1] + pxv[r].y;
            ov.z = Os[so + 2] + pxv[r].z;
            ov.w = Os[so + 3] + pxv[r].w;
            *reinterpret_cast<float4*>(out + gg) = ov;
        }
        __syncthreads();
    }
}

// ---------------------------------------------------------------------------
extern "C" void kernel_launch(void* const* d_in, const int* in_sizes, int n_in,
                              void* d_out, int out_size)
{
    const float* x     = (const float*)d_in[0];
    const float* gamma = (const float*)d_in[1];
    const float* beta  = (const float*)d_in[2];
    const float* wq    = (const float*)d_in[3];
    const float* wk    = (const float*)d_in[4];
    const float* wv    = (const float*)d_in[5];
    const float* wproj = (const float*)d_in[6];
    float* out = (float*)d_out;

    cudaFuncSetAttribute(gemm_uv_f16, cudaFuncAttributeMaxDynamicSharedMemorySize,
                         GEMM_SMEM);
    cudaFuncSetAttribute(attn_mma, cudaFuncAttributeMaxDynamicSharedMemorySize,
                         ATTN_SMEM_FLOATS * 4);

    prep_w2<<<1024, 256>>>(wq, wk, wv, wproj, gamma, beta);
    conv_x16<<<dim3(512, 8, B_), 256>>>(x);
    reduce_stats<<<128, 128>>>();
    gemm_uv_f16<<<dim3(8, 256, B_), 128, GEMM_SMEM>>>();
    attn_mma<<<512, 256, ATTN_SMEM_FLOATS * 4>>>(x, gamma, beta, out);
}